// round 1
// baseline (speedup 1.0000x reference)
#include <cuda_runtime.h>
#include <cuda_bf16.h>
#include <math.h>

// ---------------------------------------------------------------------------
// TweetyBERT forward: conv stack + 4-layer transformer w/ relative attention
// B=4, T=1000, DM=512, H=8, DEPTH=64, FFN=2048, L=4, EDIM=128
// ---------------------------------------------------------------------------

#define Bn 4
#define Tn 1000
#define DMn 512
#define Hn 8
#define DEPTHn 64
#define FFNn 2048
#define Ln 4
#define EDIMn 128

// -------------------- scratch (device globals; no allocs) ------------------
__device__ float g_p1[Bn * 32 * 14 * Tn];        // conv1+gelu+pool out
__device__ float g_c2[Bn * 64 * 14 * Tn];        // conv2+gelu (pre-pool)
__device__ float g_p2[Bn * 64 * Tn];             // pooled conv2
__device__ float g_x [Bn * Tn * DMn];            // residual stream
__device__ float g_xn[Bn * Tn * DMn];            // layernorm out
__device__ float g_q [Bn * Tn * DMn];
__device__ float g_k [Bn * Tn * DMn];
__device__ float g_v [Bn * Tn * DMn];
__device__ float g_ao[Bn * Tn * DMn];            // attention out (b,t,h*64+d)
__device__ float g_ff[Bn * Tn * FFNn];           // ffn mid

__device__ __forceinline__ float gelu_exact(float x) {
    return 0.5f * x * (1.0f + erff(x * 0.70710678118654752440f));
}

// -------------------- conv1 + gelu + maxpool(14) ---------------------------
// spec (4,1,196,1000) -> p1 (4,32,14,1000)
__global__ void conv1_pool_kernel(const float* __restrict__ spec,
                                  const float* __restrict__ w1,
                                  const float* __restrict__ b1,
                                  float* __restrict__ p1) {
    int t  = blockIdx.x * 256 + threadIdx.x;
    int hp = blockIdx.y;                  // 0..13
    int bc = blockIdx.z;                  // b*32 + c
    int b = bc >> 5, c = bc & 31;
    __shared__ float w[25];
    if (threadIdx.x < 25) w[threadIdx.x] = w1[c * 25 + threadIdx.x];
    __syncthreads();
    if (t >= Tn) return;
    float bias = b1[c];
    float mx = -1e30f;
    #pragma unroll 1
    for (int hh = 0; hh < 14; hh++) {
        int h = hp * 14 + hh;
        float acc = bias;
        #pragma unroll
        for (int kh = 0; kh < 5; kh++) {
            int hi = h + kh - 2;
            if (hi < 0 || hi >= 196) continue;
            const float* srow = spec + ((size_t)b * 196 + hi) * Tn;
            #pragma unroll
            for (int kw = 0; kw < 5; kw++) {
                int ti = t + kw - 2;
                if (ti >= 0 && ti < Tn) acc += srow[ti] * w[kh * 5 + kw];
            }
        }
        mx = fmaxf(mx, gelu_exact(acc));
    }
    p1[(((size_t)(b * 32 + c)) * 14 + hp) * Tn + t] = mx;
}

// -------------------- conv2 + gelu ------------------------------------------
// p1 (4,32,14,1000) -> c2 (4,64,14,1000)
__global__ void conv2_kernel(const float* __restrict__ p1,
                             const float* __restrict__ w2,
                             const float* __restrict__ b2,
                             float* __restrict__ c2) {
    int t = blockIdx.x * 256 + threadIdx.x;
    int h = blockIdx.y;                  // 0..13
    int z = blockIdx.z;                  // b*64 + co
    int b = z >> 6, co = z & 63;
    __shared__ float ws[800];
    for (int i = threadIdx.x; i < 800; i += 256) ws[i] = w2[(size_t)co * 800 + i];
    __syncthreads();
    if (t >= Tn) return;
    float acc = b2[co];
    #pragma unroll 1
    for (int ci = 0; ci < 32; ci++) {
        const float* pbase = p1 + ((size_t)(b * 32 + ci) * 14) * Tn;
        const float* wci = ws + ci * 25;
        #pragma unroll
        for (int kh = 0; kh < 5; kh++) {
            int hi = h + kh - 2;
            if (hi < 0 || hi >= 14) continue;
            const float* prow = pbase + (size_t)hi * Tn;
            const float* wrow = wci + kh * 5;
            #pragma unroll
            for (int kw = 0; kw < 5; kw++) {
                int ti = t + kw - 2;
                if (ti >= 0 && ti < Tn) acc += prow[ti] * wrow[kw];
            }
        }
    }
    c2[(((size_t)z) * 14 + h) * Tn + t] = gelu_exact(acc);
}

// -------------------- pool over h (14 -> 1) --------------------------------
__global__ void pool2_kernel(const float* __restrict__ c2, float* __restrict__ p2) {
    int idx = blockIdx.x * 256 + threadIdx.x;     // 0..255999
    if (idx >= Bn * 64 * Tn) return;
    int t = idx % Tn;
    int z = idx / Tn;
    const float* base = c2 + (size_t)z * 14 * Tn + t;
    float m = -1e30f;
    #pragma unroll
    for (int h = 0; h < 14; h++) m = fmaxf(m, base[(size_t)h * Tn]);
    p2[idx] = m;
}

// -------------------- proj: x[b,t,:] = W(512x64) @ p2[b,:,t] + b ----------
__global__ void proj_kernel(const float* __restrict__ p2,
                            const float* __restrict__ pw,
                            const float* __restrict__ pb,
                            float* __restrict__ x) {
    int bt = blockIdx.x;                  // b*1000 + t
    int b = bt / Tn, t = bt % Tn;
    int tid = threadIdx.x;
    __shared__ float col[64];
    if (tid < 64) col[tid] = p2[((size_t)b * 64 + tid) * Tn + t];
    __syncthreads();
    for (int m = tid; m < DMn; m += 256) {
        float acc = pb[m];
        const float* wr = pw + (size_t)m * 64;
        #pragma unroll
        for (int ci = 0; ci < 64; ci++) acc += wr[ci] * col[ci];
        x[(size_t)bt * DMn + m] = acc;
    }
}

// -------------------- layernorm (rows of 512) ------------------------------
__global__ void ln_kernel(const float* __restrict__ x,
                          const float* __restrict__ g,
                          const float* __restrict__ bta,
                          float* __restrict__ y) {
    int row = blockIdx.x;
    int tid = threadIdx.x;                // 256
    const float* xr = x + (size_t)row * DMn;
    float v0 = xr[tid], v1 = xr[tid + 256];
    __shared__ float red[256];
    red[tid] = v0 + v1;
    __syncthreads();
    #pragma unroll
    for (int o = 128; o > 0; o >>= 1) {
        if (tid < o) red[tid] += red[tid + o];
        __syncthreads();
    }
    float mu = red[0] * (1.0f / DMn);
    __syncthreads();
    float d0 = v0 - mu, d1 = v1 - mu;
    red[tid] = d0 * d0 + d1 * d1;
    __syncthreads();
    #pragma unroll
    for (int o = 128; o > 0; o >>= 1) {
        if (tid < o) red[tid] += red[tid + o];
        __syncthreads();
    }
    float inv = rsqrtf(red[0] * (1.0f / DMn) + 1e-5f);
    y[(size_t)row * DMn + tid]       = g[tid] * d0 * inv + bta[tid];
    y[(size_t)row * DMn + tid + 256] = g[tid + 256] * d1 * inv + bta[tid + 256];
}

// -------------------- SGEMM: C(MxN) = A(MxK) @ W(N,K)^T + bias [epi] -------
// epi: 0 = bias ; 1 = bias+relu ; 2 = bias + residual add
#define BM 128
#define BN 128
#define BK 8
__global__ void sgemm_nt(const float* __restrict__ A, const float* __restrict__ W,
                         const float* __restrict__ bias, const float* __restrict__ resid,
                         float* __restrict__ C, int M, int N, int K, int epi) {
    __shared__ float As[BK][BM];
    __shared__ float Bs[BK][BN];
    int tid = threadIdx.x;                // 256
    int brow = blockIdx.y * BM;
    int bcol = blockIdx.x * BN;
    int tm = (tid / 16) * 8;
    int tn = (tid % 16) * 8;
    float acc[8][8];
    #pragma unroll
    for (int i = 0; i < 8; i++)
        #pragma unroll
        for (int j = 0; j < 8; j++) acc[i][j] = 0.f;

    int lr = tid >> 1;                    // 0..127
    int lk = (tid & 1) * 4;               // 0 or 4

    for (int k0 = 0; k0 < K; k0 += BK) {
        float4 av;
        int ar = brow + lr;
        if (ar < M) av = *(const float4*)(A + (size_t)ar * K + k0 + lk);
        else av = make_float4(0.f, 0.f, 0.f, 0.f);
        As[lk + 0][lr] = av.x; As[lk + 1][lr] = av.y;
        As[lk + 2][lr] = av.z; As[lk + 3][lr] = av.w;
        float4 bv = *(const float4*)(W + (size_t)(bcol + lr) * K + k0 + lk);
        Bs[lk + 0][lr] = bv.x; Bs[lk + 1][lr] = bv.y;
        Bs[lk + 2][lr] = bv.z; Bs[lk + 3][lr] = bv.w;
        __syncthreads();
        #pragma unroll
        for (int kk = 0; kk < BK; kk++) {
            float a[8], bb[8];
            #pragma unroll
            for (int i = 0; i < 8; i++) a[i] = As[kk][tm + i];
            #pragma unroll
            for (int j = 0; j < 8; j++) bb[j] = Bs[kk][tn + j];
            #pragma unroll
            for (int i = 0; i < 8; i++)
                #pragma unroll
                for (int j = 0; j < 8; j++) acc[i][j] += a[i] * bb[j];
        }
        __syncthreads();
    }
    #pragma unroll 1
    for (int i = 0; i < 8; i++) {
        int r = brow + tm + i;
        if (r >= M) break;
        #pragma unroll
        for (int j = 0; j < 8; j++) {
            int c = bcol + tn + j;
            float v = acc[i][j] + bias[c];
            if (epi == 1) v = fmaxf(v, 0.f);
            else if (epi == 2) v += resid[(size_t)r * N + c];
            C[(size_t)r * N + c] = v;
        }
    }
}

// -------------------- attention with relative-position skew ----------------
// One block per (b,h,i). Q/K/V laid out (b,t,h*64+d) row-major (4000x512).
__global__ void attn_kernel(const float* __restrict__ Q, const float* __restrict__ Kb,
                            const float* __restrict__ Vb, const float* __restrict__ Er,
                            float* __restrict__ O) {
    int i = blockIdx.x, h = blockIdx.y, b = blockIdx.z;
    int tid = threadIdx.x;                // 256
    __shared__ float q0[64], q1[64];
    __shared__ float sl[Tn];
    __shared__ float red[256];
    __shared__ float ored[4][64];
    size_t qoff = ((size_t)(b * Tn + i)) * DMn + h * DEPTHn;
    if (tid < 64) {
        q0[tid] = Q[qoff + tid];
        q1[tid] = (i + 1 < Tn) ? Q[qoff + DMn + tid] : 0.f;
    }
    __syncthreads();

    float lmax = -1e30f;
    for (int t = tid; t < Tn; t += 256) {
        const float4* kr = (const float4*)(Kb + ((size_t)(b * Tn + t)) * DMn + h * DEPTHn);
        const float* erp = nullptr;
        const float* qq = q0;
        if (t <= i)            erp = Er + (size_t)(Tn - 1 - i + t) * DEPTHn;
        else if (t > i + 1)  { erp = Er + (size_t)(t - i - 2) * DEPTHn; qq = q1; }
        float qk = 0.f, sr = 0.f;
        #pragma unroll
        for (int d4 = 0; d4 < 16; d4++) {
            float4 kv = kr[d4];
            qk += q0[d4 * 4 + 0] * kv.x + q0[d4 * 4 + 1] * kv.y
                + q0[d4 * 4 + 2] * kv.z + q0[d4 * 4 + 3] * kv.w;
        }
        if (erp) {
            const float4* e4 = (const float4*)erp;
            #pragma unroll
            for (int d4 = 0; d4 < 16; d4++) {
                float4 ev = e4[d4];
                sr += qq[d4 * 4 + 0] * ev.x + qq[d4 * 4 + 1] * ev.y
                    + qq[d4 * 4 + 2] * ev.z + qq[d4 * 4 + 3] * ev.w;
            }
        }
        float lg = (qk + sr) * 0.125f;    // scale = 1/sqrt(64)
        sl[t] = lg;
        lmax = fmaxf(lmax, lg);
    }
    red[tid] = lmax;
    __syncthreads();
    #pragma unroll
    for (int o = 128; o > 0; o >>= 1) {
        if (tid < o) red[tid] = fmaxf(red[tid], red[tid + o]);
        __syncthreads();
    }
    float m = red[0];
    __syncthreads();

    float lsum = 0.f;
    for (int t = tid; t < Tn; t += 256) {
        float p = expf(sl[t] - m);
        sl[t] = p;
        lsum += p;
    }
    red[tid] = lsum;
    __syncthreads();
    #pragma unroll
    for (int o = 128; o > 0; o >>= 1) {
        if (tid < o) red[tid] += red[tid + o];
        __syncthreads();
    }
    float denom = red[0];
    __syncthreads();

    int d = tid & 63, qd = tid >> 6;      // 4 chunks of 250 t each
    float acc = 0.f;
    for (int t = qd * 250; t < qd * 250 + 250; t++)
        acc += sl[t] * Vb[((size_t)(b * Tn + t)) * DMn + h * DEPTHn + d];
    ored[qd][d] = acc;
    __syncthreads();
    if (qd == 0) {
        float o = (ored[0][d] + ored[1][d] + ored[2][d] + ored[3][d]) / denom;
        O[qoff + d] = o;
    }
}

// ---------------------------------------------------------------------------
static float* symaddr(const void* sym) {
    void* p = nullptr;
    cudaGetSymbolAddress(&p, sym);
    return (float*)p;
}

extern "C" void kernel_launch(void* const* d_in, const int* in_sizes, int n_in,
                              void* d_out, int out_size) {
    const float* spec     = (const float*)d_in[0];
    const float* conv1_w  = (const float*)d_in[1];
    const float* conv1_b  = (const float*)d_in[2];
    const float* conv2_w  = (const float*)d_in[3];
    const float* conv2_b  = (const float*)d_in[4];
    const float* proj_w   = (const float*)d_in[5];
    const float* proj_b   = (const float*)d_in[6];
    const float* ln1_g    = (const float*)d_in[7];
    const float* ln1_b    = (const float*)d_in[8];
    const float* qw       = (const float*)d_in[9];
    const float* kw       = (const float*)d_in[10];
    const float* vw       = (const float*)d_in[11];
    const float* dw       = (const float*)d_in[12];
    const float* qb       = (const float*)d_in[13];
    const float* kb       = (const float*)d_in[14];
    const float* vb       = (const float*)d_in[15];
    const float* db       = (const float*)d_in[16];
    const float* Er       = (const float*)d_in[17];
    const float* ln2_g    = (const float*)d_in[18];
    const float* ln2_b    = (const float*)d_in[19];
    const float* f1w      = (const float*)d_in[20];
    const float* f1b      = (const float*)d_in[21];
    const float* f2w      = (const float*)d_in[22];
    const float* f2b      = (const float*)d_in[23];
    const float* deproj_w = (const float*)d_in[24];
    const float* deproj_b = (const float*)d_in[25];
    float* out = (float*)d_out;

    float* p1 = symaddr(g_p1);
    float* c2 = symaddr(g_c2);
    float* p2 = symaddr(g_p2);
    float* x  = symaddr(g_x);
    float* xn = symaddr(g_xn);
    float* q  = symaddr(g_q);
    float* k  = symaddr(g_k);
    float* v  = symaddr(g_v);
    float* ao = symaddr(g_ao);
    float* ff = symaddr(g_ff);

    const int M = Bn * Tn;                // 4000

    // conv front-end
    conv1_pool_kernel<<<dim3(4, 14, Bn * 32), 256>>>(spec, conv1_w, conv1_b, p1);
    conv2_kernel<<<dim3(4, 14, Bn * 64), 256>>>(p1, conv2_w, conv2_b, c2);
    pool2_kernel<<<dim3((Bn * 64 * Tn + 255) / 256), 256>>>(c2, p2);
    proj_kernel<<<dim3(M), 256>>>(p2, proj_w, proj_b, x);

    dim3 g512(DMn / BN, (M + BM - 1) / BM);    // (4, 32)
    dim3 gffn(FFNn / BN, (M + BM - 1) / BM);   // (16, 32)
    dim3 gdep(EDIMn / BN, (M + BM - 1) / BM);  // (1, 32)

    for (int l = 0; l < Ln; l++) {
        const float* qwl = qw + (size_t)l * DMn * DMn;
        const float* kwl = kw + (size_t)l * DMn * DMn;
        const float* vwl = vw + (size_t)l * DMn * DMn;
        const float* dwl = dw + (size_t)l * DMn * DMn;
        const float* Erl = Er + (size_t)l * Tn * DEPTHn;

        ln_kernel<<<M, 256>>>(x, ln1_g + l * DMn, ln1_b + l * DMn, xn);
        sgemm_nt<<<g512, 256>>>(xn, qwl, qb + l * DMn, nullptr, q, M, DMn, DMn, 0);
        sgemm_nt<<<g512, 256>>>(xn, kwl, kb + l * DMn, nullptr, k, M, DMn, DMn, 0);
        sgemm_nt<<<g512, 256>>>(xn, vwl, vb + l * DMn, nullptr, v, M, DMn, DMn, 0);
        attn_kernel<<<dim3(Tn, Hn, Bn), 256>>>(q, k, v, Erl, ao);
        sgemm_nt<<<g512, 256>>>(ao, dwl, db + l * DMn, x, x, M, DMn, DMn, 2);
        ln_kernel<<<M, 256>>>(x, ln2_g + l * DMn, ln2_b + l * DMn, xn);
        sgemm_nt<<<gffn, 256>>>(xn, f1w + (size_t)l * FFNn * DMn, f1b + l * FFNn,
                                nullptr, ff, M, FFNn, DMn, 1);
        sgemm_nt<<<g512, 256>>>(ff, f2w + (size_t)l * DMn * FFNn, f2b + l * DMn,
                                x, x, M, DMn, FFNn, 2);
    }

    sgemm_nt<<<gdep, 256>>>(x, deproj_w, deproj_b, nullptr, out, M, EDIMn, DMn, 0);
}

// round 2
// speedup vs baseline: 2.1851x; 2.1851x over previous
#include <cuda_runtime.h>
#include <cuda_bf16.h>
#include <math.h>

// ---------------------------------------------------------------------------
// TweetyBERT forward: conv stack + 4-layer transformer w/ relative attention
// B=4, T=1000, DM=512, H=8, DEPTH=64, FFN=2048, L=4, EDIM=128
// ---------------------------------------------------------------------------

#define Bn 4
#define Tn 1000
#define DMn 512
#define Hn 8
#define DEPTHn 64
#define FFNn 2048
#define Ln 4
#define EDIMn 128

// -------------------- scratch (device globals; no allocs) ------------------
__device__ float g_p1[Bn * 32 * 14 * Tn];        // conv1+gelu+pool out
__device__ float g_c2[Bn * 64 * 14 * Tn];        // conv2+gelu (pre-pool)
__device__ float g_pt[Bn * Tn * 64];             // pooled conv2, transposed (b,t,c)
__device__ float g_x [Bn * Tn * DMn];            // residual stream
__device__ float g_xn[Bn * Tn * DMn];            // layernorm out
__device__ float g_q [Bn * Tn * DMn];
__device__ float g_k [Bn * Tn * DMn];
__device__ float g_v [Bn * Tn * DMn];
__device__ float g_ao[Bn * Tn * DMn];            // attention out (b,t,h*64+d)
__device__ float g_ff[Bn * Tn * FFNn];           // ffn mid
__device__ float g_S [Bn * Hn * Tn * Tn];        // scores / probs (in-place)
__device__ float g_P [Bn * Hn * Tn * Tn];        // Q @ Er^T

__device__ __forceinline__ float gelu_exact(float x) {
    return 0.5f * x * (1.0f + erff(x * 0.70710678118654752440f));
}

// -------------------- conv1 + gelu + maxpool(14) ---------------------------
__global__ void conv1_pool_kernel(const float* __restrict__ spec,
                                  const float* __restrict__ w1,
                                  const float* __restrict__ b1,
                                  float* __restrict__ p1) {
    int t  = blockIdx.x * 256 + threadIdx.x;
    int hp = blockIdx.y;                  // 0..13
    int bc = blockIdx.z;                  // b*32 + c
    int b = bc >> 5, c = bc & 31;
    __shared__ float w[25];
    if (threadIdx.x < 25) w[threadIdx.x] = w1[c * 25 + threadIdx.x];
    __syncthreads();
    if (t >= Tn) return;
    float bias = b1[c];
    float mx = -1e30f;
    #pragma unroll 1
    for (int hh = 0; hh < 14; hh++) {
        int h = hp * 14 + hh;
        float acc = bias;
        #pragma unroll
        for (int kh = 0; kh < 5; kh++) {
            int hi = h + kh - 2;
            if (hi < 0 || hi >= 196) continue;
            const float* srow = spec + ((size_t)b * 196 + hi) * Tn;
            #pragma unroll
            for (int kw = 0; kw < 5; kw++) {
                int ti = t + kw - 2;
                if (ti >= 0 && ti < Tn) acc += srow[ti] * w[kh * 5 + kw];
            }
        }
        mx = fmaxf(mx, gelu_exact(acc));
    }
    p1[(((size_t)(b * 32 + c)) * 14 + hp) * Tn + t] = mx;
}

// -------------------- conv2 + gelu -----------------------------------------
__global__ void conv2_kernel(const float* __restrict__ p1,
                             const float* __restrict__ w2,
                             const float* __restrict__ b2,
                             float* __restrict__ c2) {
    int t = blockIdx.x * 256 + threadIdx.x;
    int h = blockIdx.y;                  // 0..13
    int z = blockIdx.z;                  // b*64 + co
    int b = z >> 6, co = z & 63;
    __shared__ float ws[800];
    for (int i = threadIdx.x; i < 800; i += 256) ws[i] = w2[(size_t)co * 800 + i];
    __syncthreads();
    if (t >= Tn) return;
    float acc = b2[co];
    #pragma unroll 1
    for (int ci = 0; ci < 32; ci++) {
        const float* pbase = p1 + ((size_t)(b * 32 + ci) * 14) * Tn;
        const float* wci = ws + ci * 25;
        #pragma unroll
        for (int kh = 0; kh < 5; kh++) {
            int hi = h + kh - 2;
            if (hi < 0 || hi >= 14) continue;
            const float* prow = pbase + (size_t)hi * Tn;
            const float* wrow = wci + kh * 5;
            #pragma unroll
            for (int kw = 0; kw < 5; kw++) {
                int ti = t + kw - 2;
                if (ti >= 0 && ti < Tn) acc += prow[ti] * wrow[kw];
            }
        }
    }
    c2[(((size_t)z) * 14 + h) * Tn + t] = gelu_exact(acc);
}

// -------------------- pool over h (14 -> 1), write transposed (b,t,c) ------
__global__ void pool2t_kernel(const float* __restrict__ c2, float* __restrict__ pt) {
    int idx = blockIdx.x * 256 + threadIdx.x;     // over b*64*1000
    if (idx >= Bn * 64 * Tn) return;
    int t = idx % Tn;
    int z = idx / Tn;                     // b*64 + c
    int b = z >> 6, c = z & 63;
    const float* base = c2 + (size_t)z * 14 * Tn + t;
    float m = -1e30f;
    #pragma unroll
    for (int h = 0; h < 14; h++) m = fmaxf(m, base[(size_t)h * Tn]);
    pt[((size_t)b * Tn + t) * 64 + c] = m;
}

// -------------------- layernorm (rows of 512) ------------------------------
__global__ void ln_kernel(const float* __restrict__ x,
                          const float* __restrict__ g,
                          const float* __restrict__ bta,
                          float* __restrict__ y) {
    int row = blockIdx.x;
    int tid = threadIdx.x;                // 256
    const float* xr = x + (size_t)row * DMn;
    float v0 = xr[tid], v1 = xr[tid + 256];
    __shared__ float red[256];
    red[tid] = v0 + v1;
    __syncthreads();
    #pragma unroll
    for (int o = 128; o > 0; o >>= 1) {
        if (tid < o) red[tid] += red[tid + o];
        __syncthreads();
    }
    float mu = red[0] * (1.0f / DMn);
    __syncthreads();
    float d0 = v0 - mu, d1 = v1 - mu;
    red[tid] = d0 * d0 + d1 * d1;
    __syncthreads();
    #pragma unroll
    for (int o = 128; o > 0; o >>= 1) {
        if (tid < o) red[tid] += red[tid + o];
        __syncthreads();
    }
    float inv = rsqrtf(red[0] * (1.0f / DMn) + 1e-5f);
    y[(size_t)row * DMn + tid]       = g[tid] * d0 * inv + bta[tid];
    y[(size_t)row * DMn + tid + 256] = g[tid + 256] * d1 * inv + bta[tid + 256];
}

// -------------------- SGEMM: C(MxN) = A(MxK) @ W(N,K)^T + bias [epi] -------
// epi: 0 = bias ; 1 = bias+relu ; 2 = bias + residual add
// Double-buffered shared tiles, 128x128x8, 8x8 per-thread.
#define BM 128
#define BN 128
#define BK 8
__global__ __launch_bounds__(256, 2)
void sgemm_nt(const float* __restrict__ A, const float* __restrict__ W,
              const float* __restrict__ bias, const float* __restrict__ resid,
              float* __restrict__ C, int M, int N, int K, int epi) {
    __shared__ __align__(16) float As[2][BK][BM];
    __shared__ __align__(16) float Bs[2][BK][BN];
    int tid = threadIdx.x;                // 256
    int brow = blockIdx.y * BM;
    int bcol = blockIdx.x * BN;
    int tm = (tid / 16) * 8;
    int tn = (tid % 16) * 8;
    float acc[8][8];
    #pragma unroll
    for (int i = 0; i < 8; i++)
        #pragma unroll
        for (int j = 0; j < 8; j++) acc[i][j] = 0.f;

    int lr = tid >> 1;                    // 0..127
    int lk = (tid & 1) * 4;               // 0 or 4
    int ar = brow + lr;

    // prologue: tile k0 = 0
    float4 av = (ar < M) ? *(const float4*)(A + (size_t)ar * K + lk)
                         : make_float4(0.f, 0.f, 0.f, 0.f);
    float4 bv = *(const float4*)(W + (size_t)(bcol + lr) * K + lk);
    int buf = 0;
    As[0][lk + 0][lr] = av.x; As[0][lk + 1][lr] = av.y;
    As[0][lk + 2][lr] = av.z; As[0][lk + 3][lr] = av.w;
    Bs[0][lk + 0][lr] = bv.x; Bs[0][lk + 1][lr] = bv.y;
    Bs[0][lk + 2][lr] = bv.z; Bs[0][lk + 3][lr] = bv.w;
    __syncthreads();

    for (int k0 = BK; k0 <= K; k0 += BK) {
        bool more = (k0 < K);
        float4 av2, bv2;
        if (more) {
            av2 = (ar < M) ? *(const float4*)(A + (size_t)ar * K + k0 + lk)
                           : make_float4(0.f, 0.f, 0.f, 0.f);
            bv2 = *(const float4*)(W + (size_t)(bcol + lr) * K + k0 + lk);
        }
        #pragma unroll
        for (int kk = 0; kk < BK; kk++) {
            float4 a0 = *(const float4*)&As[buf][kk][tm];
            float4 a1 = *(const float4*)&As[buf][kk][tm + 4];
            float4 b0 = *(const float4*)&Bs[buf][kk][tn];
            float4 b1 = *(const float4*)&Bs[buf][kk][tn + 4];
            float a[8] = {a0.x, a0.y, a0.z, a0.w, a1.x, a1.y, a1.z, a1.w};
            float bb[8] = {b0.x, b0.y, b0.z, b0.w, b1.x, b1.y, b1.z, b1.w};
            #pragma unroll
            for (int i = 0; i < 8; i++)
                #pragma unroll
                for (int j = 0; j < 8; j++) acc[i][j] += a[i] * bb[j];
        }
        if (more) {
            buf ^= 1;
            As[buf][lk + 0][lr] = av2.x; As[buf][lk + 1][lr] = av2.y;
            As[buf][lk + 2][lr] = av2.z; As[buf][lk + 3][lr] = av2.w;
            Bs[buf][lk + 0][lr] = bv2.x; Bs[buf][lk + 1][lr] = bv2.y;
            Bs[buf][lk + 2][lr] = bv2.z; Bs[buf][lk + 3][lr] = bv2.w;
            __syncthreads();
        }
    }
    #pragma unroll 1
    for (int i = 0; i < 8; i++) {
        int r = brow + tm + i;
        if (r >= M) break;
        #pragma unroll
        for (int j = 0; j < 8; j++) {
            int c = bcol + tn + j;
            float v = acc[i][j] + bias[c];
            if (epi == 1) v = fmaxf(v, 0.f);
            else if (epi == 2) v += resid[(size_t)r * N + c];
            C[(size_t)r * N + c] = v;
        }
    }
}

// -------------------- batched NT GEMM (no bias): 32 batches (b,h) ---------
// C[z] (MxN) = A[z](MxK) @ B[z](NxK)^T   with per-(b,h) base offsets
__global__ __launch_bounds__(256, 2)
void sgemm_bnt(const float* __restrict__ A, const float* __restrict__ Bm,
               float* __restrict__ C, int M, int N, int K,
               int lda, int ldb, int ldc,
               long sAb, long sAh, long sBb, long sBh, long sCb, long sCh) {
    int zb = blockIdx.z >> 3, zh = blockIdx.z & 7;
    A  += (size_t)zb * sAb + (size_t)zh * sAh;
    Bm += (size_t)zb * sBb + (size_t)zh * sBh;
    C  += (size_t)zb * sCb + (size_t)zh * sCh;

    __shared__ __align__(16) float As[2][BK][BM];
    __shared__ __align__(16) float Bs[2][BK][BN];
    int tid = threadIdx.x;
    int brow = blockIdx.y * BM;
    int bcol = blockIdx.x * BN;
    int tm = (tid / 16) * 8;
    int tn = (tid % 16) * 8;
    float acc[8][8];
    #pragma unroll
    for (int i = 0; i < 8; i++)
        #pragma unroll
        for (int j = 0; j < 8; j++) acc[i][j] = 0.f;

    int lr = tid >> 1;
    int lk = (tid & 1) * 4;
    int ar = brow + lr;
    int br = bcol + lr;

    float4 av = (ar < M) ? *(const float4*)(A + (size_t)ar * lda + lk)
                         : make_float4(0.f, 0.f, 0.f, 0.f);
    float4 bv = (br < N) ? *(const float4*)(Bm + (size_t)br * ldb + lk)
                         : make_float4(0.f, 0.f, 0.f, 0.f);
    int buf = 0;
    As[0][lk + 0][lr] = av.x; As[0][lk + 1][lr] = av.y;
    As[0][lk + 2][lr] = av.z; As[0][lk + 3][lr] = av.w;
    Bs[0][lk + 0][lr] = bv.x; Bs[0][lk + 1][lr] = bv.y;
    Bs[0][lk + 2][lr] = bv.z; Bs[0][lk + 3][lr] = bv.w;
    __syncthreads();

    for (int k0 = BK; k0 <= K; k0 += BK) {
        bool more = (k0 < K);
        float4 av2, bv2;
        if (more) {
            av2 = (ar < M) ? *(const float4*)(A + (size_t)ar * lda + k0 + lk)
                           : make_float4(0.f, 0.f, 0.f, 0.f);
            bv2 = (br < N) ? *(const float4*)(Bm + (size_t)br * ldb + k0 + lk)
                           : make_float4(0.f, 0.f, 0.f, 0.f);
        }
        #pragma unroll
        for (int kk = 0; kk < BK; kk++) {
            float4 a0 = *(const float4*)&As[buf][kk][tm];
            float4 a1 = *(const float4*)&As[buf][kk][tm + 4];
            float4 b0 = *(const float4*)&Bs[buf][kk][tn];
            float4 b1 = *(const float4*)&Bs[buf][kk][tn + 4];
            float a[8] = {a0.x, a0.y, a0.z, a0.w, a1.x, a1.y, a1.z, a1.w};
            float bb[8] = {b0.x, b0.y, b0.z, b0.w, b1.x, b1.y, b1.z, b1.w};
            #pragma unroll
            for (int i = 0; i < 8; i++)
                #pragma unroll
                for (int j = 0; j < 8; j++) acc[i][j] += a[i] * bb[j];
        }
        if (more) {
            buf ^= 1;
            As[buf][lk + 0][lr] = av2.x; As[buf][lk + 1][lr] = av2.y;
            As[buf][lk + 2][lr] = av2.z; As[buf][lk + 3][lr] = av2.w;
            Bs[buf][lk + 0][lr] = bv2.x; Bs[buf][lk + 1][lr] = bv2.y;
            Bs[buf][lk + 2][lr] = bv2.z; Bs[buf][lk + 3][lr] = bv2.w;
            __syncthreads();
        }
    }
    #pragma unroll 1
    for (int i = 0; i < 8; i++) {
        int r = brow + tm + i;
        if (r >= M) break;
        #pragma unroll
        for (int j = 0; j < 8; j++) {
            int c = bcol + tn + j;
            if (c < N) C[(size_t)r * ldc + c] = acc[i][j];
        }
    }
}

// -------------------- softmax with skewed relative scores ------------------
// row r = bh*1000 + i.  logits = (S[r][t] + Srel)*0.125
// Srel: t<=i -> P[bh][i][999-i+t]; t==i+1 -> 0; t>i+1 -> P[bh][i+1][t-i-2]
__global__ void softmax_skew_kernel(const float* __restrict__ S,
                                    const float* __restrict__ P,
                                    float* __restrict__ Aout) {
    int r = blockIdx.x;                   // 0..31999
    int i = r % Tn;
    int tid = threadIdx.x;                // 256
    const float* srow = S + (size_t)r * Tn;
    const float* pi   = P + (size_t)r * Tn;
    const float* pi1  = pi + Tn;
    __shared__ float sl[Tn];
    __shared__ float red[256];

    float lmax = -1e30f;
    for (int t = tid; t < Tn; t += 256) {
        float srel;
        if (t <= i)          srel = pi[Tn - 1 - i + t];
        else if (t == i + 1) srel = 0.f;
        else                 srel = pi1[t - i - 2];
        float lg = (srow[t] + srel) * 0.125f;
        sl[t] = lg;
        lmax = fmaxf(lmax, lg);
    }
    red[tid] = lmax;
    __syncthreads();
    #pragma unroll
    for (int o = 128; o > 0; o >>= 1) {
        if (tid < o) red[tid] = fmaxf(red[tid], red[tid + o]);
        __syncthreads();
    }
    float m = red[0];
    __syncthreads();

    float lsum = 0.f;
    for (int t = tid; t < Tn; t += 256) {
        float p = __expf(sl[t] - m);
        sl[t] = p;
        lsum += p;
    }
    red[tid] = lsum;
    __syncthreads();
    #pragma unroll
    for (int o = 128; o > 0; o >>= 1) {
        if (tid < o) red[tid] += red[tid + o];
        __syncthreads();
    }
    float inv = 1.0f / red[0];
    __syncthreads();

    float* arow = Aout + (size_t)r * Tn;
    for (int t = tid; t < Tn; t += 256) arow[t] = sl[t] * inv;
}

// -------------------- AV: O = probs(1000x1000) @ V(1000x64) ----------------
// grid (rowTiles=16, 32 batches). 64x64 tile, BK=32, 4x4 per thread.
__global__ __launch_bounds__(256, 4)
void av_nn_kernel(const float* __restrict__ Pr, const float* __restrict__ V,
                  float* __restrict__ O) {
    int bh = blockIdx.y;
    int b = bh >> 3, h = bh & 7;
    const float* Ab = Pr + (size_t)bh * Tn * Tn;
    const float* Vb = V + (size_t)b * Tn * DMn + h * DEPTHn;
    float* Ob = O + (size_t)b * Tn * DMn + h * DEPTHn;

    __shared__ float As[32][65];
    __shared__ float Vs[32][64];
    int tid = threadIdx.x;
    int tm = (tid >> 4) << 2;             // 0..60
    int tn = (tid & 15) << 2;             // 0..60
    int i0 = blockIdx.x * 64;
    float acc[4][4];
    #pragma unroll
    for (int a = 0; a < 4; a++)
        #pragma unroll
        for (int c = 0; c < 4; c++) acc[a][c] = 0.f;

    for (int k0 = 0; k0 < Tn; k0 += 32) {
        for (int idx = tid; idx < 64 * 32; idx += 256) {
            int rr = idx >> 5, kk = idx & 31;
            int row = i0 + rr, col = k0 + kk;
            As[kk][rr] = (row < Tn && col < Tn) ? Ab[(size_t)row * Tn + col] : 0.f;
        }
        for (int idx = tid; idx < 32 * 64; idx += 256) {
            int kk = idx >> 6, d = idx & 63;
            int t = k0 + kk;
            Vs[kk][d] = (t < Tn) ? Vb[(size_t)t * DMn + d] : 0.f;
        }
        __syncthreads();
        #pragma unroll
        for (int kk = 0; kk < 32; kk++) {
            float a0 = As[kk][tm], a1 = As[kk][tm + 1], a2 = As[kk][tm + 2], a3 = As[kk][tm + 3];
            float v0 = Vs[kk][tn], v1 = Vs[kk][tn + 1], v2 = Vs[kk][tn + 2], v3 = Vs[kk][tn + 3];
            acc[0][0] += a0 * v0; acc[0][1] += a0 * v1; acc[0][2] += a0 * v2; acc[0][3] += a0 * v3;
            acc[1][0] += a1 * v0; acc[1][1] += a1 * v1; acc[1][2] += a1 * v2; acc[1][3] += a1 * v3;
            acc[2][0] += a2 * v0; acc[2][1] += a2 * v1; acc[2][2] += a2 * v2; acc[2][3] += a2 * v3;
            acc[3][0] += a3 * v0; acc[3][1] += a3 * v1; acc[3][2] += a3 * v2; acc[3][3] += a3 * v3;
        }
        __syncthreads();
    }
    #pragma unroll
    for (int a = 0; a < 4; a++) {
        int row = i0 + tm + a;
        if (row < Tn) {
            #pragma unroll
            for (int c = 0; c < 4; c++) Ob[(size_t)row * DMn + tn + c] = acc[a][c];
        }
    }
}

// ---------------------------------------------------------------------------
static float* symaddr(const void* sym) {
    void* p = nullptr;
    cudaGetSymbolAddress(&p, sym);
    return (float*)p;
}

extern "C" void kernel_launch(void* const* d_in, const int* in_sizes, int n_in,
                              void* d_out, int out_size) {
    const float* spec     = (const float*)d_in[0];
    const float* conv1_w  = (const float*)d_in[1];
    const float* conv1_b  = (const float*)d_in[2];
    const float* conv2_w  = (const float*)d_in[3];
    const float* conv2_b  = (const float*)d_in[4];
    const float* proj_w   = (const float*)d_in[5];
    const float* proj_b   = (const float*)d_in[6];
    const float* ln1_g    = (const float*)d_in[7];
    const float* ln1_b    = (const float*)d_in[8];
    const float* qw       = (const float*)d_in[9];
    const float* kw       = (const float*)d_in[10];
    const float* vw       = (const float*)d_in[11];
    const float* dw       = (const float*)d_in[12];
    const float* qb       = (const float*)d_in[13];
    const float* kb       = (const float*)d_in[14];
    const float* vb       = (const float*)d_in[15];
    const float* db       = (const float*)d_in[16];
    const float* Er       = (const float*)d_in[17];
    const float* ln2_g    = (const float*)d_in[18];
    const float* ln2_b    = (const float*)d_in[19];
    const float* f1w      = (const float*)d_in[20];
    const float* f1b      = (const float*)d_in[21];
    const float* f2w      = (const float*)d_in[22];
    const float* f2b      = (const float*)d_in[23];
    const float* deproj_w = (const float*)d_in[24];
    const float* deproj_b = (const float*)d_in[25];
    float* out = (float*)d_out;

    float* p1 = symaddr(g_p1);
    float* c2 = symaddr(g_c2);
    float* pt = symaddr(g_pt);
    float* x  = symaddr(g_x);
    float* xn = symaddr(g_xn);
    float* q  = symaddr(g_q);
    float* k  = symaddr(g_k);
    float* v  = symaddr(g_v);
    float* ao = symaddr(g_ao);
    float* ff = symaddr(g_ff);
    float* S  = symaddr(g_S);
    float* P  = symaddr(g_P);

    const int M = Bn * Tn;                // 4000

    // conv front-end
    conv1_pool_kernel<<<dim3(4, 14, Bn * 32), 256>>>(spec, conv1_w, conv1_b, p1);
    conv2_kernel<<<dim3(4, 14, Bn * 64), 256>>>(p1, conv2_w, conv2_b, c2);
    pool2t_kernel<<<dim3((Bn * 64 * Tn + 255) / 256), 256>>>(c2, pt);
    sgemm_nt<<<dim3(DMn / BN, (M + BM - 1) / BM), 256>>>(pt, proj_w, proj_b, nullptr,
                                                         x, M, DMn, 64, 0);

    dim3 g512(DMn / BN, (M + BM - 1) / BM);    // (4, 32)
    dim3 gffn(FFNn / BN, (M + BM - 1) / BM);   // (16, 32)
    dim3 gdep(EDIMn / BN, (M + BM - 1) / BM);  // (1, 32)
    dim3 gatt(8, 8, Bn * Hn);                  // 1000x1000 tiles x 32 batches
    const long sQb = (long)Tn * DMn;           // 512000
    const long sSb = (long)Hn * Tn * Tn;       // 8e6
    const long sSh = (long)Tn * Tn;            // 1e6

    for (int l = 0; l < Ln; l++) {
        const float* qwl = qw + (size_t)l * DMn * DMn;
        const float* kwl = kw + (size_t)l * DMn * DMn;
        const float* vwl = vw + (size_t)l * DMn * DMn;
        const float* dwl = dw + (size_t)l * DMn * DMn;
        const float* Erl = Er + (size_t)l * Tn * DEPTHn;

        ln_kernel<<<M, 256>>>(x, ln1_g + l * DMn, ln1_b + l * DMn, xn);
        sgemm_nt<<<g512, 256>>>(xn, qwl, qb + l * DMn, nullptr, q, M, DMn, DMn, 0);
        sgemm_nt<<<g512, 256>>>(xn, kwl, kb + l * DMn, nullptr, k, M, DMn, DMn, 0);
        sgemm_nt<<<g512, 256>>>(xn, vwl, vb + l * DMn, nullptr, v, M, DMn, DMn, 0);

        // S = Q @ K^T   (batched over b,h)
        sgemm_bnt<<<gatt, 256>>>(q, k, S, Tn, Tn, DEPTHn, DMn, DMn, Tn,
                                 sQb, DEPTHn, sQb, DEPTHn, sSb, sSh);
        // P = Q @ Er^T  (Er shared across b,h)
        sgemm_bnt<<<gatt, 256>>>(q, Erl, P, Tn, Tn, DEPTHn, DMn, DEPTHn, Tn,
                                 sQb, DEPTHn, 0, 0, sSb, sSh);
        // softmax with skew (in-place on S)
        softmax_skew_kernel<<<Bn * Hn * Tn, 256>>>(S, P, S);
        // O = probs @ V
        av_nn_kernel<<<dim3(16, Bn * Hn), 256>>>(S, v, ao);

        sgemm_nt<<<g512, 256>>>(ao, dwl, db + l * DMn, x, x, M, DMn, DMn, 2);
        ln_kernel<<<M, 256>>>(x, ln2_g + l * DMn, ln2_b + l * DMn, xn);
        sgemm_nt<<<gffn, 256>>>(xn, f1w + (size_t)l * FFNn * DMn, f1b + l * FFNn,
                                nullptr, ff, M, FFNn, DMn, 1);
        sgemm_nt<<<g512, 256>>>(ff, f2w + (size_t)l * DMn * FFNn, f2b + l * DMn,
                                x, x, M, DMn, FFNn, 2);
    }

    sgemm_nt<<<gdep, 256>>>(x, deproj_w, deproj_b, nullptr, out, M, EDIMn, DMn, 0);
}

// round 3
// speedup vs baseline: 3.8945x; 1.7823x over previous
#include <cuda_runtime.h>
#include <cuda_bf16.h>
#include <math.h>
#include <stdint.h>

// ---------------------------------------------------------------------------
// TweetyBERT forward: conv stack + 4-layer transformer w/ relative attention
// All GEMMs on tensor cores via mma.sync tf32 with 3xTF32 accuracy split.
// B=4, T=1000, DM=512, H=8, DEPTH=64, FFN=2048, L=4, EDIM=128
// ---------------------------------------------------------------------------

#define Bn 4
#define Tn 1000
#define DMn 512
#define Hn 8
#define DEPTHn 64
#define FFNn 2048
#define Ln 4
#define EDIMn 128

// -------------------- scratch (device globals; no allocs) ------------------
__device__ float g_p1[Bn * 32 * 14 * Tn];
__device__ float g_c2[Bn * 64 * 14 * Tn];
__device__ float g_pt[Bn * Tn * 64];
__device__ float g_x [Bn * Tn * DMn];
__device__ float g_xn[Bn * Tn * DMn];
__device__ float g_q [Bn * Tn * DMn];
__device__ float g_k [Bn * Tn * DMn];
__device__ float g_v [Bn * Tn * DMn];
__device__ float g_ao[Bn * Tn * DMn];
__device__ float g_ff[Bn * Tn * FFNn];
__device__ float g_S [Bn * Hn * Tn * Tn];
__device__ float g_P [Bn * Hn * Tn * Tn];

__device__ __forceinline__ float gelu_exact(float x) {
    return 0.5f * x * (1.0f + erff(x * 0.70710678118654752440f));
}

__device__ __forceinline__ float tf32_rna(float x) {
    uint32_t u;
    asm("cvt.rna.tf32.f32 %0, %1;" : "=r"(u) : "f"(x));
    return __uint_as_float(u);
}

__device__ __forceinline__ void mma_tf32(float* c, const uint32_t* a, const uint32_t* b) {
    asm volatile(
        "mma.sync.aligned.m16n8k8.row.col.f32.tf32.tf32.f32 "
        "{%0,%1,%2,%3}, {%4,%5,%6,%7}, {%8,%9}, {%0,%1,%2,%3};\n"
        : "+f"(c[0]), "+f"(c[1]), "+f"(c[2]), "+f"(c[3])
        : "r"(a[0]), "r"(a[1]), "r"(a[2]), "r"(a[3]), "r"(b[0]), "r"(b[1]));
}

// -------------------- conv1 + gelu + maxpool(14) ---------------------------
__global__ void conv1_pool_kernel(const float* __restrict__ spec,
                                  const float* __restrict__ w1,
                                  const float* __restrict__ b1,
                                  float* __restrict__ p1) {
    int t  = blockIdx.x * 256 + threadIdx.x;
    int hp = blockIdx.y;
    int bc = blockIdx.z;
    int b = bc >> 5, c = bc & 31;
    __shared__ float w[25];
    if (threadIdx.x < 25) w[threadIdx.x] = w1[c * 25 + threadIdx.x];
    __syncthreads();
    if (t >= Tn) return;
    float bias = b1[c];
    float mx = -1e30f;
    #pragma unroll 1
    for (int hh = 0; hh < 14; hh++) {
        int h = hp * 14 + hh;
        float acc = bias;
        #pragma unroll
        for (int kh = 0; kh < 5; kh++) {
            int hi = h + kh - 2;
            if (hi < 0 || hi >= 196) continue;
            const float* srow = spec + ((size_t)b * 196 + hi) * Tn;
            #pragma unroll
            for (int kw = 0; kw < 5; kw++) {
                int ti = t + kw - 2;
                if (ti >= 0 && ti < Tn) acc += srow[ti] * w[kh * 5 + kw];
            }
        }
        mx = fmaxf(mx, gelu_exact(acc));
    }
    p1[(((size_t)(b * 32 + c)) * 14 + hp) * Tn + t] = mx;
}

// -------------------- conv2 + gelu -----------------------------------------
__global__ void conv2_kernel(const float* __restrict__ p1,
                             const float* __restrict__ w2,
                             const float* __restrict__ b2,
                             float* __restrict__ c2) {
    int t = blockIdx.x * 256 + threadIdx.x;
    int h = blockIdx.y;
    int z = blockIdx.z;
    int b = z >> 6, co = z & 63;
    __shared__ float ws[800];
    for (int i = threadIdx.x; i < 800; i += 256) ws[i] = w2[(size_t)co * 800 + i];
    __syncthreads();
    if (t >= Tn) return;
    float acc = b2[co];
    #pragma unroll 1
    for (int ci = 0; ci < 32; ci++) {
        const float* pbase = p1 + ((size_t)(b * 32 + ci) * 14) * Tn;
        const float* wci = ws + ci * 25;
        #pragma unroll
        for (int kh = 0; kh < 5; kh++) {
            int hi = h + kh - 2;
            if (hi < 0 || hi >= 14) continue;
            const float* prow = pbase + (size_t)hi * Tn;
            const float* wrow = wci + kh * 5;
            #pragma unroll
            for (int kw = 0; kw < 5; kw++) {
                int ti = t + kw - 2;
                if (ti >= 0 && ti < Tn) acc += prow[ti] * wrow[kw];
            }
        }
    }
    c2[(((size_t)z) * 14 + h) * Tn + t] = gelu_exact(acc);
}

// -------------------- pool over h (14 -> 1), write transposed (b,t,c) ------
__global__ void pool2t_kernel(const float* __restrict__ c2, float* __restrict__ pt) {
    int idx = blockIdx.x * 256 + threadIdx.x;
    if (idx >= Bn * 64 * Tn) return;
    int t = idx % Tn;
    int z = idx / Tn;
    int b = z >> 6, c = z & 63;
    const float* base = c2 + (size_t)z * 14 * Tn + t;
    float m = -1e30f;
    #pragma unroll
    for (int h = 0; h < 14; h++) m = fmaxf(m, base[(size_t)h * Tn]);
    pt[((size_t)b * Tn + t) * 64 + c] = m;
}

// -------------------- layernorm (rows of 512) ------------------------------
__global__ void ln_kernel(const float* __restrict__ x,
                          const float* __restrict__ g,
                          const float* __restrict__ bta,
                          float* __restrict__ y) {
    int row = blockIdx.x;
    int tid = threadIdx.x;
    const float* xr = x + (size_t)row * DMn;
    float v0 = xr[tid], v1 = xr[tid + 256];
    __shared__ float red[256];
    red[tid] = v0 + v1;
    __syncthreads();
    #pragma unroll
    for (int o = 128; o > 0; o >>= 1) {
        if (tid < o) red[tid] += red[tid + o];
        __syncthreads();
    }
    float mu = red[0] * (1.0f / DMn);
    __syncthreads();
    float d0 = v0 - mu, d1 = v1 - mu;
    red[tid] = d0 * d0 + d1 * d1;
    __syncthreads();
    #pragma unroll
    for (int o = 128; o > 0; o >>= 1) {
        if (tid < o) red[tid] += red[tid + o];
        __syncthreads();
    }
    float inv = rsqrtf(red[0] * (1.0f / DMn) + 1e-5f);
    y[(size_t)row * DMn + tid]       = g[tid] * d0 * inv + bta[tid];
    y[(size_t)row * DMn + tid + 256] = g[tid + 256] * d1 * inv + bta[tid + 256];
}

// -------------------- generic tf32x3 tensor-core GEMM ----------------------
// C(MxN) = A(MxK) @ op(B) [+bias][+relu|+resid]
// bnn=0: B is (N,K) row-major (NT, i.e. C = A @ B^T)
// bnn=1: B is (K,N) row-major (NN)
// Batched over blockIdx.z with split strides (z = zb*8 + zh).
// epi: 0 bias, 1 bias+relu, 2 bias+resid, 3 none
#define TBK 8
#define PADW 136
__global__ __launch_bounds__(256, 2)
void tf32_gemm(const float* __restrict__ A, const float* __restrict__ B,
               const float* __restrict__ bias, const float* __restrict__ resid,
               float* __restrict__ C, int M, int N, int K,
               int lda, int ldb, int ldc,
               long sA1, long sA2, long sB1, long sB2, long sC1, long sC2,
               int epi, int bnn)
{
    int z = blockIdx.z, zb = z >> 3, zh = z & 7;
    A += (size_t)zb * sA1 + (size_t)zh * sA2;
    B += (size_t)zb * sB1 + (size_t)zh * sB2;
    C += (size_t)zb * sC1 + (size_t)zh * sC2;

    __shared__ float Ah[2][TBK][PADW], Al[2][TBK][PADW];
    __shared__ float Bh[2][TBK][PADW], Bl[2][TBK][PADW];

    int tid = threadIdx.x, lane = tid & 31, w = tid >> 5;
    int warp_m = (w & 1) * 64, warp_n = (w >> 1) * 32;
    int brow = blockIdx.y * 128, bcol = blockIdx.x * 128;

    float acc[4][4][4];
    #pragma unroll
    for (int a = 0; a < 4; a++)
        #pragma unroll
        for (int b2 = 0; b2 < 4; b2++)
            #pragma unroll
            for (int c2 = 0; c2 < 4; c2++) acc[a][b2][c2] = 0.f;

    int lr = tid >> 1, lk = (tid & 1) * 4;
    int ar = brow + lr;
    int nbr = bcol + lr;                 // NT B row
    int bkk = tid >> 5;                  // NN: k within tile (0..7)
    int bn4 = (tid & 31) * 4;            // NN: n offset (0..124)

    const float4 f4z = make_float4(0.f, 0.f, 0.f, 0.f);

#define FETCH_A(k0, dst) \
    dst = (ar < M) ? *(const float4*)(A + (size_t)ar * lda + (k0) + lk) : f4z;
#define FETCH_B(k0, dst) \
    if (!bnn) dst = (nbr < N) ? *(const float4*)(B + (size_t)nbr * ldb + (k0) + lk) : f4z; \
    else dst = (bn4 < N && (k0) + bkk < K) ? *(const float4*)(B + (size_t)((k0) + bkk) * ldb + bn4) : f4z;

#define SPLIT_STORE(arrH, arrL, buf, kidx, cidx, val) { \
    float _h = tf32_rna(val); \
    arrH[buf][kidx][cidx] = _h; \
    arrL[buf][kidx][cidx] = tf32_rna((val) - _h); }

#define STORE_A(buf, v) { \
    SPLIT_STORE(Ah, Al, buf, lk + 0, lr, (v).x); \
    SPLIT_STORE(Ah, Al, buf, lk + 1, lr, (v).y); \
    SPLIT_STORE(Ah, Al, buf, lk + 2, lr, (v).z); \
    SPLIT_STORE(Ah, Al, buf, lk + 3, lr, (v).w); }

#define STORE_B(buf, v) \
    if (!bnn) { \
        SPLIT_STORE(Bh, Bl, buf, lk + 0, lr, (v).x); \
        SPLIT_STORE(Bh, Bl, buf, lk + 1, lr, (v).y); \
        SPLIT_STORE(Bh, Bl, buf, lk + 2, lr, (v).z); \
        SPLIT_STORE(Bh, Bl, buf, lk + 3, lr, (v).w); \
    } else { \
        SPLIT_STORE(Bh, Bl, buf, bkk, bn4 + 0, (v).x); \
        SPLIT_STORE(Bh, Bl, buf, bkk, bn4 + 1, (v).y); \
        SPLIT_STORE(Bh, Bl, buf, bkk, bn4 + 2, (v).z); \
        SPLIT_STORE(Bh, Bl, buf, bkk, bn4 + 3, (v).w); }

    float4 va, vb;
    FETCH_A(0, va); FETCH_B(0, vb);
    STORE_A(0, va); STORE_B(0, vb);
    __syncthreads();

    int buf = 0;
    for (int k0 = TBK; k0 <= K; k0 += TBK) {
        bool more = (k0 < K);
        float4 na, nb;
        if (more) { FETCH_A(k0, na); FETCH_B(k0, nb); }

        int kr = lane & 3;
        uint32_t bhf[4][2], blf[4][2];
        #pragma unroll
        for (int nt = 0; nt < 4; nt++) {
            int col = warp_n + nt * 8 + (lane >> 2);
            bhf[nt][0] = __float_as_uint(Bh[buf][kr][col]);
            bhf[nt][1] = __float_as_uint(Bh[buf][kr + 4][col]);
            blf[nt][0] = __float_as_uint(Bl[buf][kr][col]);
            blf[nt][1] = __float_as_uint(Bl[buf][kr + 4][col]);
        }
        #pragma unroll
        for (int mt = 0; mt < 4; mt++) {
            int row = warp_m + mt * 16 + (lane >> 2);
            uint32_t ah[4], al[4];
            ah[0] = __float_as_uint(Ah[buf][kr][row]);
            ah[1] = __float_as_uint(Ah[buf][kr][row + 8]);
            ah[2] = __float_as_uint(Ah[buf][kr + 4][row]);
            ah[3] = __float_as_uint(Ah[buf][kr + 4][row + 8]);
            al[0] = __float_as_uint(Al[buf][kr][row]);
            al[1] = __float_as_uint(Al[buf][kr][row + 8]);
            al[2] = __float_as_uint(Al[buf][kr + 4][row]);
            al[3] = __float_as_uint(Al[buf][kr + 4][row + 8]);
            #pragma unroll
            for (int nt = 0; nt < 4; nt++) {
                mma_tf32(acc[mt][nt], al, bhf[nt]);   // alo*bhi
                mma_tf32(acc[mt][nt], ah, blf[nt]);   // ahi*blo
                mma_tf32(acc[mt][nt], ah, bhf[nt]);   // ahi*bhi
            }
        }
        if (more) {
            buf ^= 1;
            STORE_A(buf, na); STORE_B(buf, nb);
            __syncthreads();
        }
    }

    // epilogue
    #pragma unroll
    for (int mt = 0; mt < 4; mt++) {
        int r0 = brow + warp_m + mt * 16 + (lane >> 2);
        #pragma unroll
        for (int nt = 0; nt < 4; nt++) {
            int c0 = bcol + warp_n + nt * 8 + (lane & 3) * 2;
            #pragma unroll
            for (int half = 0; half < 2; half++) {
                int rr = r0 + half * 8;
                if (rr >= M) continue;
                #pragma unroll
                for (int jj = 0; jj < 2; jj++) {
                    int cc = c0 + jj;
                    if (cc >= N) continue;
                    float vv = acc[mt][nt][half * 2 + jj];
                    if (epi != 3) vv += bias[cc];
                    if (epi == 1) vv = fmaxf(vv, 0.f);
                    else if (epi == 2) vv += resid[(size_t)rr * ldc + cc];
                    C[(size_t)rr * ldc + cc] = vv;
                }
            }
        }
    }
#undef FETCH_A
#undef FETCH_B
#undef SPLIT_STORE
#undef STORE_A
#undef STORE_B
}

// -------------------- softmax with skewed relative scores ------------------
__global__ void softmax_skew_kernel(const float* __restrict__ S,
                                    const float* __restrict__ P,
                                    float* __restrict__ Aout) {
    int r = blockIdx.x;
    int i = r % Tn;
    int tid = threadIdx.x;
    const float* srow = S + (size_t)r * Tn;
    const float* pi   = P + (size_t)r * Tn;
    const float* pi1  = pi + Tn;
    __shared__ float sl[Tn];
    __shared__ float red[256];

    float lmax = -1e30f;
    for (int t = tid; t < Tn; t += 256) {
        float srel;
        if (t <= i)          srel = pi[Tn - 1 - i + t];
        else if (t == i + 1) srel = 0.f;
        else                 srel = pi1[t - i - 2];
        float lg = (srow[t] + srel) * 0.125f;
        sl[t] = lg;
        lmax = fmaxf(lmax, lg);
    }
    red[tid] = lmax;
    __syncthreads();
    #pragma unroll
    for (int o = 128; o > 0; o >>= 1) {
        if (tid < o) red[tid] = fmaxf(red[tid], red[tid + o]);
        __syncthreads();
    }
    float m = red[0];
    __syncthreads();

    float lsum = 0.f;
    for (int t = tid; t < Tn; t += 256) {
        float p = __expf(sl[t] - m);
        sl[t] = p;
        lsum += p;
    }
    red[tid] = lsum;
    __syncthreads();
    #pragma unroll
    for (int o = 128; o > 0; o >>= 1) {
        if (tid < o) red[tid] += red[tid + o];
        __syncthreads();
    }
    float inv = 1.0f / red[0];
    __syncthreads();

    float* arow = Aout + (size_t)r * Tn;
    for (int t = tid; t < Tn; t += 256) arow[t] = sl[t] * inv;
}

// ---------------------------------------------------------------------------
static float* symaddr(const void* sym) {
    void* p = nullptr;
    cudaGetSymbolAddress(&p, sym);
    return (float*)p;
}

extern "C" void kernel_launch(void* const* d_in, const int* in_sizes, int n_in,
                              void* d_out, int out_size) {
    const float* spec     = (const float*)d_in[0];
    const float* conv1_w  = (const float*)d_in[1];
    const float* conv1_b  = (const float*)d_in[2];
    const float* conv2_w  = (const float*)d_in[3];
    const float* conv2_b  = (const float*)d_in[4];
    const float* proj_w   = (const float*)d_in[5];
    const float* proj_b   = (const float*)d_in[6];
    const float* ln1_g    = (const float*)d_in[7];
    const float* ln1_b    = (const float*)d_in[8];
    const float* qw       = (const float*)d_in[9];
    const float* kw       = (const float*)d_in[10];
    const float* vw       = (const float*)d_in[11];
    const float* dw       = (const float*)d_in[12];
    const float* qb       = (const float*)d_in[13];
    const float* kb       = (const float*)d_in[14];
    const float* vb       = (const float*)d_in[15];
    const float* db       = (const float*)d_in[16];
    const float* Er       = (const float*)d_in[17];
    const float* ln2_g    = (const float*)d_in[18];
    const float* ln2_b    = (const float*)d_in[19];
    const float* f1w      = (const float*)d_in[20];
    const float* f1b      = (const float*)d_in[21];
    const float* f2w      = (const float*)d_in[22];
    const float* f2b      = (const float*)d_in[23];
    const float* deproj_w = (const float*)d_in[24];
    const float* deproj_b = (const float*)d_in[25];
    float* out = (float*)d_out;

    float* p1 = symaddr(g_p1);
    float* c2 = symaddr(g_c2);
    float* pt = symaddr(g_pt);
    float* x  = symaddr(g_x);
    float* xn = symaddr(g_xn);
    float* q  = symaddr(g_q);
    float* k  = symaddr(g_k);
    float* v  = symaddr(g_v);
    float* ao = symaddr(g_ao);
    float* ff = symaddr(g_ff);
    float* S  = symaddr(g_S);
    float* P  = symaddr(g_P);

    const int M = Bn * Tn;                // 4000
    const long sQb = (long)Tn * DMn;      // batch stride in q/k/v/ao
    const long sSb = (long)Hn * Tn * Tn;  // batch stride in S/P
    const long sSh = (long)Tn * Tn;

    // conv front-end
    conv1_pool_kernel<<<dim3(4, 14, Bn * 32), 256>>>(spec, conv1_w, conv1_b, p1);
    conv2_kernel<<<dim3(4, 14, Bn * 64), 256>>>(p1, conv2_w, conv2_b, c2);
    pool2t_kernel<<<dim3((Bn * 64 * Tn + 255) / 256), 256>>>(c2, pt);
    tf32_gemm<<<dim3(4, 32, 1), 256>>>(pt, proj_w, proj_b, nullptr, x,
                                       M, DMn, 64, 64, 64, DMn,
                                       0, 0, 0, 0, 0, 0, 0, 0);

    dim3 g512(4, 32, 1);
    dim3 gffn(16, 32, 1);
    dim3 gscore(8, 8, Bn * Hn);
    dim3 gav(1, 8, Bn * Hn);

    for (int l = 0; l < Ln; l++) {
        const float* qwl = qw + (size_t)l * DMn * DMn;
        const float* kwl = kw + (size_t)l * DMn * DMn;
        const float* vwl = vw + (size_t)l * DMn * DMn;
        const float* dwl = dw + (size_t)l * DMn * DMn;
        const float* Erl = Er + (size_t)l * Tn * DEPTHn;

        ln_kernel<<<M, 256>>>(x, ln1_g + l * DMn, ln1_b + l * DMn, xn);
        tf32_gemm<<<g512, 256>>>(xn, qwl, qb + l * DMn, nullptr, q,
                                 M, DMn, DMn, DMn, DMn, DMn,
                                 0, 0, 0, 0, 0, 0, 0, 0);
        tf32_gemm<<<g512, 256>>>(xn, kwl, kb + l * DMn, nullptr, k,
                                 M, DMn, DMn, DMn, DMn, DMn,
                                 0, 0, 0, 0, 0, 0, 0, 0);
        tf32_gemm<<<g512, 256>>>(xn, vwl, vb + l * DMn, nullptr, v,
                                 M, DMn, DMn, DMn, DMn, DMn,
                                 0, 0, 0, 0, 0, 0, 0, 0);

        // S = Q @ K^T   (batched over b,h)
        tf32_gemm<<<gscore, 256>>>(q, k, nullptr, nullptr, S,
                                   Tn, Tn, DEPTHn, DMn, DMn, Tn,
                                   sQb, DEPTHn, sQb, DEPTHn, sSb, sSh, 3, 0);
        // P = Q @ Er^T  (Er shared across b,h)
        tf32_gemm<<<gscore, 256>>>(q, Erl, nullptr, nullptr, P,
                                   Tn, Tn, DEPTHn, DMn, DEPTHn, Tn,
                                   sQb, DEPTHn, 0, 0, sSb, sSh, 3, 0);
        // softmax with skew (in-place on S)
        softmax_skew_kernel<<<Bn * Hn * Tn, 256>>>(S, P, S);
        // O = probs @ V   (NN: B is (K,N)-major slice of v)
        tf32_gemm<<<gav, 256>>>(S, v, nullptr, nullptr, ao,
                                Tn, DEPTHn, Tn, Tn, DMn, DMn,
                                sSb, sSh, sQb, DEPTHn, sQb, DEPTHn, 3, 1);

        tf32_gemm<<<g512, 256>>>(ao, dwl, db + l * DMn, x, x,
                                 M, DMn, DMn, DMn, DMn, DMn,
                                 0, 0, 0, 0, 0, 0, 2, 0);
        ln_kernel<<<M, 256>>>(x, ln2_g + l * DMn, ln2_b + l * DMn, xn);
        tf32_gemm<<<gffn, 256>>>(xn, f1w + (size_t)l * FFNn * DMn, f1b + l * FFNn,
                                 nullptr, ff, M, FFNn, DMn, DMn, DMn, FFNn,
                                 0, 0, 0, 0, 0, 0, 1, 0);
        tf32_gemm<<<g512, 256>>>(ff, f2w + (size_t)l * DMn * FFNn, f2b + l * DMn,
                                 x, x, M, DMn, FFNn, FFNn, FFNn, DMn,
                                 0, 0, 0, 0, 0, 0, 2, 0);
    }

    tf32_gemm<<<dim3(1, 32, 1), 256>>>(x, deproj_w, deproj_b, nullptr, out,
                                       M, EDIMn, DMn, DMn, DMn, EDIMn,
                                       0, 0, 0, 0, 0, 0, 0, 0);
}

// round 4
// speedup vs baseline: 5.5218x; 1.4178x over previous
#include <cuda_runtime.h>
#include <cuda_fp16.h>
#include <math.h>
#include <stdint.h>

// ---------------------------------------------------------------------------
// TweetyBERT forward. Residual-stream GEMMs: tf32x3 tensor cores.
// Attention scores/probs/AV: fp16 tensor cores (precision budget allows).
// B=4, T=1000, DM=512, H=8, DEPTH=64, FFN=2048, L=4, EDIM=128
// ---------------------------------------------------------------------------

#define Bn 4
#define Tn 1000
#define DMn 512
#define Hn 8
#define DEPTHn 64
#define FFNn 2048
#define Ln 4
#define EDIMn 128

// -------------------- scratch (device globals; no allocs) ------------------
__device__ float g_p1[Bn * 32 * 14 * Tn];
__device__ float g_c2[Bn * 64 * 14 * Tn];
__device__ float g_pt[Bn * Tn * 64];
__device__ float g_x [Bn * Tn * DMn];
__device__ float g_xn[Bn * Tn * DMn];
__device__ float g_q [Bn * Tn * DMn];
__device__ float g_k [Bn * Tn * DMn];
__device__ float g_v [Bn * Tn * DMn];
__device__ float g_ao[Bn * Tn * DMn];
__device__ float g_ff[Bn * Tn * FFNn];
__device__ __half g_S [Bn * Hn * Tn * Tn];   // scores -> probs (fp16)
__device__ __half g_P [Bn * Hn * Tn * Tn];   // Q @ Er^T (fp16)

__device__ __forceinline__ float gelu_exact(float x) {
    return 0.5f * x * (1.0f + erff(x * 0.70710678118654752440f));
}

__device__ __forceinline__ float tf32_rna(float x) {
    uint32_t u;
    asm("cvt.rna.tf32.f32 %0, %1;" : "=r"(u) : "f"(x));
    return __uint_as_float(u);
}

__device__ __forceinline__ void mma_tf32(float* c, const uint32_t* a, const uint32_t* b) {
    asm volatile(
        "mma.sync.aligned.m16n8k8.row.col.f32.tf32.tf32.f32 "
        "{%0,%1,%2,%3}, {%4,%5,%6,%7}, {%8,%9}, {%0,%1,%2,%3};\n"
        : "+f"(c[0]), "+f"(c[1]), "+f"(c[2]), "+f"(c[3])
        : "r"(a[0]), "r"(a[1]), "r"(a[2]), "r"(a[3]), "r"(b[0]), "r"(b[1]));
}

__device__ __forceinline__ void mma_f16(float* c, const uint32_t* a, const uint32_t* b) {
    asm volatile(
        "mma.sync.aligned.m16n8k16.row.col.f32.f16.f16.f32 "
        "{%0,%1,%2,%3}, {%4,%5,%6,%7}, {%8,%9}, {%0,%1,%2,%3};\n"
        : "+f"(c[0]), "+f"(c[1]), "+f"(c[2]), "+f"(c[3])
        : "r"(a[0]), "r"(a[1]), "r"(a[2]), "r"(a[3]), "r"(b[0]), "r"(b[1]));
}

// -------------------- conv1 + gelu + maxpool(14) ---------------------------
__global__ void conv1_pool_kernel(const float* __restrict__ spec,
                                  const float* __restrict__ w1,
                                  const float* __restrict__ b1,
                                  float* __restrict__ p1) {
    int t  = blockIdx.x * 256 + threadIdx.x;
    int hp = blockIdx.y;
    int bc = blockIdx.z;
    int b = bc >> 5, c = bc & 31;
    __shared__ float w[25];
    if (threadIdx.x < 25) w[threadIdx.x] = w1[c * 25 + threadIdx.x];
    __syncthreads();
    if (t >= Tn) return;
    float bias = b1[c];
    float mx = -1e30f;
    #pragma unroll 1
    for (int hh = 0; hh < 14; hh++) {
        int h = hp * 14 + hh;
        float acc = bias;
        #pragma unroll
        for (int kh = 0; kh < 5; kh++) {
            int hi = h + kh - 2;
            if (hi < 0 || hi >= 196) continue;
            const float* srow = spec + ((size_t)b * 196 + hi) * Tn;
            #pragma unroll
            for (int kw = 0; kw < 5; kw++) {
                int ti = t + kw - 2;
                if (ti >= 0 && ti < Tn) acc += srow[ti] * w[kh * 5 + kw];
            }
        }
        mx = fmaxf(mx, gelu_exact(acc));
    }
    p1[(((size_t)(b * 32 + c)) * 14 + hp) * Tn + t] = mx;
}

// -------------------- conv2 + gelu (4 outputs per thread) ------------------
__global__ void conv2_kernel(const float* __restrict__ p1,
                             const float* __restrict__ w2,
                             const float* __restrict__ b2,
                             float* __restrict__ c2) {
    int t0 = threadIdx.x * 4;            // block covers t 0..1023
    int h = blockIdx.y;
    int z = blockIdx.z;
    int b = z >> 6, co = z & 63;
    __shared__ float ws[800];
    for (int i = threadIdx.x; i < 800; i += 256) ws[i] = w2[(size_t)co * 800 + i];
    __syncthreads();
    if (t0 >= Tn) return;
    float bias = b2[co];
    float acc[4] = {bias, bias, bias, bias};
    #pragma unroll 1
    for (int ci = 0; ci < 32; ci++) {
        const float* pbase = p1 + ((size_t)(b * 32 + ci) * 14) * Tn;
        const float* wci = ws + ci * 25;
        #pragma unroll
        for (int kh = 0; kh < 5; kh++) {
            int hi = h + kh - 2;
            if (hi < 0 || hi >= 14) continue;
            const float* prow = pbase + (size_t)hi * Tn;
            const float* wrow = wci + kh * 5;
            float in[8];
            #pragma unroll
            for (int u = 0; u < 8; u++) {
                int ti = t0 - 2 + u;
                in[u] = (ti >= 0 && ti < Tn) ? prow[ti] : 0.f;
            }
            #pragma unroll
            for (int kw = 0; kw < 5; kw++) {
                float wv = wrow[kw];
                acc[0] += in[kw + 0] * wv;
                acc[1] += in[kw + 1] * wv;
                acc[2] += in[kw + 2] * wv;
                acc[3] += in[kw + 3] * wv;
            }
        }
    }
    float* orow = c2 + (((size_t)z) * 14 + h) * Tn;
    #pragma unroll
    for (int o = 0; o < 4; o++)
        if (t0 + o < Tn) orow[t0 + o] = gelu_exact(acc[o]);
}

// -------------------- pool over h (14 -> 1), write transposed (b,t,c) ------
__global__ void pool2t_kernel(const float* __restrict__ c2, float* __restrict__ pt) {
    int idx = blockIdx.x * 256 + threadIdx.x;
    if (idx >= Bn * 64 * Tn) return;
    int t = idx % Tn;
    int z = idx / Tn;
    int b = z >> 6, c = z & 63;
    const float* base = c2 + (size_t)z * 14 * Tn + t;
    float m = -1e30f;
    #pragma unroll
    for (int h = 0; h < 14; h++) m = fmaxf(m, base[(size_t)h * Tn]);
    pt[((size_t)b * Tn + t) * 64 + c] = m;
}

// -------------------- layernorm (rows of 512) ------------------------------
__global__ void ln_kernel(const float* __restrict__ x,
                          const float* __restrict__ g,
                          const float* __restrict__ bta,
                          float* __restrict__ y) {
    int row = blockIdx.x;
    int tid = threadIdx.x;
    const float* xr = x + (size_t)row * DMn;
    float v0 = xr[tid], v1 = xr[tid + 256];
    __shared__ float red[256];
    red[tid] = v0 + v1;
    __syncthreads();
    #pragma unroll
    for (int o = 128; o > 0; o >>= 1) {
        if (tid < o) red[tid] += red[tid + o];
        __syncthreads();
    }
    float mu = red[0] * (1.0f / DMn);
    __syncthreads();
    float d0 = v0 - mu, d1 = v1 - mu;
    red[tid] = d0 * d0 + d1 * d1;
    __syncthreads();
    #pragma unroll
    for (int o = 128; o > 0; o >>= 1) {
        if (tid < o) red[tid] += red[tid + o];
        __syncthreads();
    }
    float inv = rsqrtf(red[0] * (1.0f / DMn) + 1e-5f);
    y[(size_t)row * DMn + tid]       = g[tid] * d0 * inv + bta[tid];
    y[(size_t)row * DMn + tid + 256] = g[tid + 256] * d1 * inv + bta[tid + 256];
}

// -------------------- generic tf32x3 tensor-core GEMM ----------------------
#define TBK 8
#define PADW 136
__global__ __launch_bounds__(256, 2)
void tf32_gemm(const float* __restrict__ A, const float* __restrict__ B,
               const float* __restrict__ bias, const float* __restrict__ resid,
               float* __restrict__ C, int M, int N, int K,
               int lda, int ldb, int ldc, int epi)
{
    __shared__ float Ah[2][TBK][PADW], Al[2][TBK][PADW];
    __shared__ float Bh[2][TBK][PADW], Bl[2][TBK][PADW];

    int tid = threadIdx.x, lane = tid & 31, w = tid >> 5;
    int warp_m = (w & 1) * 64, warp_n = (w >> 1) * 32;
    int brow = blockIdx.y * 128, bcol = blockIdx.x * 128;

    float acc[4][4][4];
    #pragma unroll
    for (int a = 0; a < 4; a++)
        #pragma unroll
        for (int b2 = 0; b2 < 4; b2++)
            #pragma unroll
            for (int c2 = 0; c2 < 4; c2++) acc[a][b2][c2] = 0.f;

    int lr = tid >> 1, lk = (tid & 1) * 4;
    int ar = brow + lr;
    int nbr = bcol + lr;
    const float4 f4z = make_float4(0.f, 0.f, 0.f, 0.f);

#define FETCH_A(k0, dst) \
    dst = (ar < M) ? *(const float4*)(A + (size_t)ar * lda + (k0) + lk) : f4z;
#define FETCH_B(k0, dst) \
    dst = (nbr < N) ? *(const float4*)(B + (size_t)nbr * ldb + (k0) + lk) : f4z;
#define SPLIT_STORE(arrH, arrL, buf, kidx, cidx, val) { \
    float _h = tf32_rna(val); \
    arrH[buf][kidx][cidx] = _h; \
    arrL[buf][kidx][cidx] = tf32_rna((val) - _h); }
#define STORE_A(buf, v) { \
    SPLIT_STORE(Ah, Al, buf, lk + 0, lr, (v).x); \
    SPLIT_STORE(Ah, Al, buf, lk + 1, lr, (v).y); \
    SPLIT_STORE(Ah, Al, buf, lk + 2, lr, (v).z); \
    SPLIT_STORE(Ah, Al, buf, lk + 3, lr, (v).w); }
#define STORE_B(buf, v) { \
    SPLIT_STORE(Bh, Bl, buf, lk + 0, lr, (v).x); \
    SPLIT_STORE(Bh, Bl, buf, lk + 1, lr, (v).y); \
    SPLIT_STORE(Bh, Bl, buf, lk + 2, lr, (v).z); \
    SPLIT_STORE(Bh, Bl, buf, lk + 3, lr, (v).w); }

    float4 va, vb;
    FETCH_A(0, va); FETCH_B(0, vb);
    STORE_A(0, va); STORE_B(0, vb);
    __syncthreads();

    int buf = 0;
    for (int k0 = TBK; k0 <= K; k0 += TBK) {
        bool more = (k0 < K);
        float4 na, nb;
        if (more) { FETCH_A(k0, na); FETCH_B(k0, nb); }

        int kr = lane & 3;
        uint32_t bhf[4][2], blf[4][2];
        #pragma unroll
        for (int nt = 0; nt < 4; nt++) {
            int col = warp_n + nt * 8 + (lane >> 2);
            bhf[nt][0] = __float_as_uint(Bh[buf][kr][col]);
            bhf[nt][1] = __float_as_uint(Bh[buf][kr + 4][col]);
            blf[nt][0] = __float_as_uint(Bl[buf][kr][col]);
            blf[nt][1] = __float_as_uint(Bl[buf][kr + 4][col]);
        }
        #pragma unroll
        for (int mt = 0; mt < 4; mt++) {
            int row = warp_m + mt * 16 + (lane >> 2);
            uint32_t ah[4], al[4];
            ah[0] = __float_as_uint(Ah[buf][kr][row]);
            ah[1] = __float_as_uint(Ah[buf][kr][row + 8]);
            ah[2] = __float_as_uint(Ah[buf][kr + 4][row]);
            ah[3] = __float_as_uint(Ah[buf][kr + 4][row + 8]);
            al[0] = __float_as_uint(Al[buf][kr][row]);
            al[1] = __float_as_uint(Al[buf][kr][row + 8]);
            al[2] = __float_as_uint(Al[buf][kr + 4][row]);
            al[3] = __float_as_uint(Al[buf][kr + 4][row + 8]);
            #pragma unroll
            for (int nt = 0; nt < 4; nt++) {
                mma_tf32(acc[mt][nt], al, bhf[nt]);
                mma_tf32(acc[mt][nt], ah, blf[nt]);
                mma_tf32(acc[mt][nt], ah, bhf[nt]);
            }
        }
        if (more) {
            buf ^= 1;
            STORE_A(buf, na); STORE_B(buf, nb);
            __syncthreads();
        }
    }

    #pragma unroll
    for (int mt = 0; mt < 4; mt++) {
        int r0 = brow + warp_m + mt * 16 + (lane >> 2);
        #pragma unroll
        for (int nt = 0; nt < 4; nt++) {
            int c0 = bcol + warp_n + nt * 8 + (lane & 3) * 2;
            #pragma unroll
            for (int half = 0; half < 2; half++) {
                int rr = r0 + half * 8;
                if (rr >= M) continue;
                #pragma unroll
                for (int jj = 0; jj < 2; jj++) {
                    int cc = c0 + jj;
                    if (cc >= N) continue;
                    float vv = acc[mt][nt][half * 2 + jj] + bias[cc];
                    if (epi == 1) vv = fmaxf(vv, 0.f);
                    else if (epi == 2) vv += resid[(size_t)rr * ldc + cc];
                    C[(size_t)rr * ldc + cc] = vv;
                }
            }
        }
    }
#undef FETCH_A
#undef FETCH_B
#undef SPLIT_STORE
#undef STORE_A
#undef STORE_B
}

// -------------------- fp16 score GEMM: C(MxN) = A(MxK=64) @ B(NxK=64)^T ----
// A,B fp32 in gmem (converted to fp16 in smem), C fp16. Batched over z.
#define SPADH 72
__global__ __launch_bounds__(256, 2)
void score_gemm(const float* __restrict__ A, const float* __restrict__ B,
                __half* __restrict__ C, int M, int N,
                int lda, int ldb, int ldc,
                long sA1, long sA2, long sB1, long sB2, long sC1, long sC2)
{
    int z = blockIdx.z, zb = z >> 3, zh = z & 7;
    A += (size_t)zb * sA1 + (size_t)zh * sA2;
    B += (size_t)zb * sB1 + (size_t)zh * sB2;
    C += (size_t)zb * sC1 + (size_t)zh * sC2;

    __shared__ __half As[128][SPADH];
    __shared__ __half Bs[128][SPADH];

    int tid = threadIdx.x, lane = tid & 31, w = tid >> 5;
    int warp_m = (w & 1) * 64, warp_n = (w >> 1) * 32;
    int brow = blockIdx.y * 128, bcol = blockIdx.x * 128;
    int g = lane >> 2, t2 = (lane & 3) * 2;

    // load + convert A,B tiles (K = 64)
    {
        int row = tid >> 1;
        int ar = brow + row, br = bcol + row;
        const float4 f4z = make_float4(0.f, 0.f, 0.f, 0.f);
        #pragma unroll
        for (int j = 0; j < 8; j++) {
            int col = ((tid & 1) * 8 + j) * 4;
            float4 av = (ar < M) ? *(const float4*)(A + (size_t)ar * lda + col) : f4z;
            float4 bv = (br < N) ? *(const float4*)(B + (size_t)br * ldb + col) : f4z;
            *(half2*)&As[row][col]     = __floats2half2_rn(av.x, av.y);
            *(half2*)&As[row][col + 2] = __floats2half2_rn(av.z, av.w);
            *(half2*)&Bs[row][col]     = __floats2half2_rn(bv.x, bv.y);
            *(half2*)&Bs[row][col + 2] = __floats2half2_rn(bv.z, bv.w);
        }
    }
    __syncthreads();

    float acc[4][4][4];
    #pragma unroll
    for (int a = 0; a < 4; a++)
        #pragma unroll
        for (int b2 = 0; b2 < 4; b2++)
            #pragma unroll
            for (int c2 = 0; c2 < 4; c2++) acc[a][b2][c2] = 0.f;

    #pragma unroll
    for (int ks = 0; ks < 4; ks++) {
        int k0 = ks * 16;
        uint32_t bf[4][2];
        #pragma unroll
        for (int nt = 0; nt < 4; nt++) {
            int col = warp_n + nt * 8 + g;
            bf[nt][0] = *(const uint32_t*)&Bs[col][k0 + t2];
            bf[nt][1] = *(const uint32_t*)&Bs[col][k0 + t2 + 8];
        }
        #pragma unroll
        for (int mt = 0; mt < 4; mt++) {
            int row = warp_m + mt * 16 + g;
            uint32_t af[4];
            af[0] = *(const uint32_t*)&As[row][k0 + t2];
            af[1] = *(const uint32_t*)&As[row + 8][k0 + t2];
            af[2] = *(const uint32_t*)&As[row][k0 + t2 + 8];
            af[3] = *(const uint32_t*)&As[row + 8][k0 + t2 + 8];
            #pragma unroll
            for (int nt = 0; nt < 4; nt++)
                mma_f16(acc[mt][nt], af, bf[nt]);
        }
    }

    #pragma unroll
    for (int mt = 0; mt < 4; mt++) {
        int r0 = brow + warp_m + mt * 16 + g;
        #pragma unroll
        for (int nt = 0; nt < 4; nt++) {
            int c0 = bcol + warp_n + nt * 8 + t2;
            if (c0 >= N) continue;
            #pragma unroll
            for (int half = 0; half < 2; half++) {
                int rr = r0 + half * 8;
                if (rr >= M) continue;
                *(half2*)&C[(size_t)rr * ldc + c0] =
                    __floats2half2_rn(acc[mt][nt][half * 2], acc[mt][nt][half * 2 + 1]);
            }
        }
    }
}

// -------------------- softmax with skew, warp-per-row, fp16 io -------------
__global__ void softmax_skew_h(const __half* __restrict__ S,
                               const __half* __restrict__ P,
                               __half* __restrict__ O) {
    int warp = threadIdx.x >> 5, lane = threadIdx.x & 31;
    int r = blockIdx.x * 8 + warp;
    int i = r % Tn;
    const __half* srow = S + (size_t)r * Tn;
    const __half* pi   = P + (size_t)r * Tn;
    const __half* pi1  = pi + Tn;

    float vals[32];
    float mx = -1e30f;
    #pragma unroll
    for (int j = 0; j < 32; j++) {
        int t = lane + j * 32;
        float lg = -1e30f;
        if (t < Tn) {
            float srel;
            if (t <= i)          srel = __half2float(pi[Tn - 1 - i + t]);
            else if (t == i + 1) srel = 0.f;
            else                 srel = __half2float(pi1[t - i - 2]);
            lg = (__half2float(srow[t]) + srel) * 0.125f;
        }
        vals[j] = lg;
        mx = fmaxf(mx, lg);
    }
    #pragma unroll
    for (int o = 16; o; o >>= 1) mx = fmaxf(mx, __shfl_xor_sync(0xffffffffu, mx, o));
    float sum = 0.f;
    #pragma unroll
    for (int j = 0; j < 32; j++) {
        float p = __expf(vals[j] - mx);
        vals[j] = p;
        sum += p;
    }
    #pragma unroll
    for (int o = 16; o; o >>= 1) sum += __shfl_xor_sync(0xffffffffu, sum, o);
    float inv = 1.0f / sum;
    __half* orow = O + (size_t)r * Tn;
    #pragma unroll
    for (int j = 0; j < 32; j++) {
        int t = lane + j * 32;
        if (t < Tn) orow[t] = __float2half_rn(vals[j] * inv);
    }
}

// -------------------- AV: O = probs(fp16, 1000x1000) @ V(fp32->fp16) -------
// 128x64 tile per block, BK=32 double-buffered. grid (8 rowTiles, 32 bh)
#define AVPAD 40
__global__ __launch_bounds__(256, 2)
void av_gemm(const __half* __restrict__ Pr, const float* __restrict__ V,
             float* __restrict__ O) {
    int bh = blockIdx.y;
    int b = bh >> 3, h = bh & 7;
    const __half* Ab = Pr + (size_t)bh * Tn * Tn;
    const float* Vb = V + (size_t)b * Tn * DMn + h * DEPTHn;
    float* Ob = O + (size_t)b * Tn * DMn + h * DEPTHn;
    int i0 = blockIdx.x * 128;

    __shared__ __half As[2][128][AVPAD];
    __shared__ __half Bs[2][DEPTHn][AVPAD];

    int tid = threadIdx.x, lane = tid & 31, w = tid >> 5;
    int warp_m = (w & 3) * 32, warp_n = (w >> 2) * 32;
    int g = lane >> 2, t2 = (lane & 3) * 2;

    float acc[2][4][4];
    #pragma unroll
    for (int a = 0; a < 2; a++)
        #pragma unroll
        for (int b2 = 0; b2 < 4; b2++)
            #pragma unroll
            for (int c2 = 0; c2 < 4; c2++) acc[a][b2][c2] = 0.f;

    int arow = tid >> 1;                       // A: 0..127
    int au   = (tid & 1) * 4;                  // 4 uint2 each
    int bk   = tid >> 3;                       // B: row (k) 0..31
    int bf4  = tid & 7;                        // + j*8 -> float4 idx

#define AV_LOAD(buf, kt) { \
    int k0 = (kt) * 32; \
    int garow = i0 + arow; \
    _Pragma("unroll") \
    for (int j = 0; j < 4; j++) { \
        int kh = (au + j) * 4; \
        uint2 val = make_uint2(0u, 0u); \
        if (garow < Tn) { \
            if (k0 + kh + 3 < Tn) val = *(const uint2*)(Ab + (size_t)garow * Tn + k0 + kh); \
            else { \
                __half tmp[4]; \
                _Pragma("unroll") \
                for (int e = 0; e < 4; e++) \
                    tmp[e] = (k0 + kh + e < Tn) ? Ab[(size_t)garow * Tn + k0 + kh + e] : __half(0.f); \
                val = *(uint2*)tmp; \
            } \
        } \
        *(uint2*)&As[buf][arow][kh] = val; \
    } \
    _Pragma("unroll") \
    for (int j = 0; j < 2; j++) { \
        int n0 = (bf4 + j * 8) * 4; \
        int tg = k0 + bk; \
        float4 vv = (tg < Tn) ? *(const float4*)(Vb + (size_t)tg * DMn + n0) \
                              : make_float4(0.f, 0.f, 0.f, 0.f); \
        Bs[buf][n0 + 0][bk] = __float2half_rn(vv.x); \
        Bs[buf][n0 + 1][bk] = __float2half_rn(vv.y); \
        Bs[buf][n0 + 2][bk] = __float2half_rn(vv.z); \
        Bs[buf][n0 + 3][bk] = __float2half_rn(vv.w); \
    } }

    AV_LOAD(0, 0);
    __syncthreads();

    int buf = 0;
    for (int kt = 0; kt < 32; kt++) {
        bool more = (kt < 31);
        #pragma unroll
        for (int ks = 0; ks < 2; ks++) {
            int k0 = ks * 16;
            uint32_t bf[4][2];
            #pragma unroll
            for (int nt = 0; nt < 4; nt++) {
                int col = warp_n + nt * 8 + g;
                bf[nt][0] = *(const uint32_t*)&Bs[buf][col][k0 + t2];
                bf[nt][1] = *(const uint32_t*)&Bs[buf][col][k0 + t2 + 8];
            }
            #pragma unroll
            for (int mt = 0; mt < 2; mt++) {
                int row = warp_m + mt * 16 + g;
                uint32_t af[4];
                af[0] = *(const uint32_t*)&As[buf][row][k0 + t2];
                af[1] = *(const uint32_t*)&As[buf][row + 8][k0 + t2];
                af[2] = *(const uint32_t*)&As[buf][row][k0 + t2 + 8];
                af[3] = *(const uint32_t*)&As[buf][row + 8][k0 + t2 + 8];
                #pragma unroll
                for (int nt = 0; nt < 4; nt++)
                    mma_f16(acc[mt][nt], af, bf[nt]);
            }
        }
        if (more) {
            AV_LOAD(buf ^ 1, kt + 1);
            __syncthreads();
            buf ^= 1;
        }
    }
#undef AV_LOAD

    #pragma unroll
    for (int mt = 0; mt < 2; mt++) {
        int r0 = i0 + warp_m + mt * 16 + g;
        #pragma unroll
        for (int nt = 0; nt < 4; nt++) {
            int c0 = warp_n + nt * 8 + t2;
            #pragma unroll
            for (int half = 0; half < 2; half++) {
                int rr = r0 + half * 8;
                if (rr >= Tn) continue;
                Ob[(size_t)rr * DMn + c0]     = acc[mt][nt][half * 2];
                Ob[(size_t)rr * DMn + c0 + 1] = acc[mt][nt][half * 2 + 1];
            }
        }
    }
}

// ---------------------------------------------------------------------------
static float* symaddr(const void* sym) {
    void* p = nullptr;
    cudaGetSymbolAddress(&p, sym);
    return (float*)p;
}

extern "C" void kernel_launch(void* const* d_in, const int* in_sizes, int n_in,
                              void* d_out, int out_size) {
    const float* spec     = (const float*)d_in[0];
    const float* conv1_w  = (const float*)d_in[1];
    const float* conv1_b  = (const float*)d_in[2];
    const float* conv2_w  = (const float*)d_in[3];
    const float* conv2_b  = (const float*)d_in[4];
    const float* proj_w   = (const float*)d_in[5];
    const float* proj_b   = (const float*)d_in[6];
    const float* ln1_g    = (const float*)d_in[7];
    const float* ln1_b    = (const float*)d_in[8];
    const float* qw       = (const float*)d_in[9];
    const float* kw       = (const float*)d_in[10];
    const float* vw       = (const float*)d_in[11];
    const float* dw       = (const float*)d_in[12];
    const float* qb       = (const float*)d_in[13];
    const float* kb       = (const float*)d_in[14];
    const float* vb       = (const float*)d_in[15];
    const float* db       = (const float*)d_in[16];
    const float* Er       = (const float*)d_in[17];
    const float* ln2_g    = (const float*)d_in[18];
    const float* ln2_b    = (const float*)d_in[19];
    const float* f1w      = (const float*)d_in[20];
    const float* f1b      = (const float*)d_in[21];
    const float* f2w      = (const float*)d_in[22];
    const float* f2b      = (const float*)d_in[23];
    const float* deproj_w = (const float*)d_in[24];
    const float* deproj_b = (const float*)d_in[25];
    float* out = (float*)d_out;

    float* p1 = symaddr(g_p1);
    float* c2 = symaddr(g_c2);
    float* pt = symaddr(g_pt);
    float* x  = symaddr(g_x);
    float* xn = symaddr(g_xn);
    float* q  = symaddr(g_q);
    float* k  = symaddr(g_k);
    float* v  = symaddr(g_v);
    float* ao = symaddr(g_ao);
    float* ff = symaddr(g_ff);
    __half* S = (__half*)symaddr(g_S);
    __half* P = (__half*)symaddr(g_P);

    const int M = Bn * Tn;                // 4000
    const long sQb = (long)Tn * DMn;
    const long sSb = (long)Hn * Tn * Tn;
    const long sSh = (long)Tn * Tn;

    conv1_pool_kernel<<<dim3(4, 14, Bn * 32), 256>>>(spec, conv1_w, conv1_b, p1);
    conv2_kernel<<<dim3(1, 14, Bn * 64), 256>>>(p1, conv2_w, conv2_b, c2);
    pool2t_kernel<<<dim3((Bn * 64 * Tn + 255) / 256), 256>>>(c2, pt);
    tf32_gemm<<<dim3(4, 32), 256>>>(pt, proj_w, proj_b, nullptr, x,
                                    M, DMn, 64, 64, 64, DMn, 0);

    dim3 g512(4, 32);
    dim3 gffn(16, 32);
    dim3 gscore(8, 8, Bn * Hn);

    for (int l = 0; l < Ln; l++) {
        const float* qwl = qw + (size_t)l * DMn * DMn;
        const float* kwl = kw + (size_t)l * DMn * DMn;
        const float* vwl = vw + (size_t)l * DMn * DMn;
        const float* dwl = dw + (size_t)l * DMn * DMn;
        const float* Erl = Er + (size_t)l * Tn * DEPTHn;

        ln_kernel<<<M, 256>>>(x, ln1_g + l * DMn, ln1_b + l * DMn, xn);
        tf32_gemm<<<g512, 256>>>(xn, qwl, qb + l * DMn, nullptr, q,
                                 M, DMn, DMn, DMn, DMn, DMn, 0);
        tf32_gemm<<<g512, 256>>>(xn, kwl, kb + l * DMn, nullptr, k,
                                 M, DMn, DMn, DMn, DMn, DMn, 0);
        tf32_gemm<<<g512, 256>>>(xn, vwl, vb + l * DMn, nullptr, v,
                                 M, DMn, DMn, DMn, DMn, DMn, 0);

        // S = Q @ K^T (fp16 out)
        score_gemm<<<gscore, 256>>>(q, k, S, Tn, Tn, DMn, DMn, Tn,
                                    sQb, DEPTHn, sQb, DEPTHn, sSb, sSh);
        // P = Q @ Er^T (fp16 out)
        score_gemm<<<gscore, 256>>>(q, Erl, P, Tn, Tn, DMn, DEPTHn, Tn,
                                    sQb, DEPTHn, 0, 0, sSb, sSh);
        // softmax with skew (in-place on S)
        softmax_skew_h<<<Bn * Hn * Tn / 8, 256>>>(S, P, S);
        // O = probs @ V
        av_gemm<<<dim3(8, Bn * Hn), 256>>>(S, v, ao);

        tf32_gemm<<<g512, 256>>>(ao, dwl, db + l * DMn, x, x,
                                 M, DMn, DMn, DMn, DMn, DMn, 2);
        ln_kernel<<<M, 256>>>(x, ln2_g + l * DMn, ln2_b + l * DMn, xn);
        tf32_gemm<<<gffn, 256>>>(xn, f1w + (size_t)l * FFNn * DMn, f1b + l * FFNn,
                                 nullptr, ff, M, FFNn, DMn, DMn, DMn, FFNn, 1);
        tf32_gemm<<<g512, 256>>>(ff, f2w + (size_t)l * DMn * FFNn, f2b + l * DMn,
                                 x, x, M, DMn, FFNn, FFNn, FFNn, DMn, 2);
    }

    tf32_gemm<<<dim3(1, 32), 256>>>(x, deproj_w, deproj_b, nullptr, out,
                                    M, EDIMn, DMn, DMn, DMn, EDIMn, 0);
}

// round 5
// speedup vs baseline: 6.5664x; 1.1892x over previous
#include <cuda_runtime.h>
#include <cuda_fp16.h>
#include <math.h>
#include <stdint.h>

// ---------------------------------------------------------------------------
// TweetyBERT forward. Residual GEMMs: fp16x2 (Markidis) tensor cores.
// Attention: fp16 tensor cores end-to-end (Q/K/V stored fp16).
// B=4, T=1000, DM=512, H=8, DEPTH=64, FFN=2048, L=4, EDIM=128
// ---------------------------------------------------------------------------

#define Bn 4
#define Tn 1000
#define DMn 512
#define Hn 8
#define DEPTHn 64
#define FFNn 2048
#define Ln 4
#define EDIMn 128

// -------------------- scratch (device globals; no allocs) ------------------
__device__ float  g_p1[Bn * 32 * 14 * Tn];
__device__ float  g_c2[Bn * 64 * 14 * Tn];
__device__ float  g_pt[Bn * Tn * 64];
__device__ float  g_x [Bn * Tn * DMn];
__device__ float  g_xn[Bn * Tn * DMn];
__device__ __half g_q [Bn * Tn * DMn];
__device__ __half g_k [Bn * Tn * DMn];
__device__ __half g_v [Bn * Tn * DMn];
__device__ float  g_ao[Bn * Tn * DMn];
__device__ float  g_ff[Bn * Tn * FFNn];
__device__ __half g_S [Bn * Hn * Tn * Tn];
__device__ __half g_P [Bn * Hn * Tn * Tn];
__device__ __half g_Erh[Tn * DEPTHn];

__device__ __forceinline__ float gelu_exact(float x) {
    return 0.5f * x * (1.0f + erff(x * 0.70710678118654752440f));
}

__device__ __forceinline__ void mma_f16(float* c, const uint32_t* a, const uint32_t* b) {
    asm volatile(
        "mma.sync.aligned.m16n8k16.row.col.f32.f16.f16.f32 "
        "{%0,%1,%2,%3}, {%4,%5,%6,%7}, {%8,%9}, {%0,%1,%2,%3};\n"
        : "+f"(c[0]), "+f"(c[1]), "+f"(c[2]), "+f"(c[3])
        : "r"(a[0]), "r"(a[1]), "r"(a[2]), "r"(a[3]), "r"(b[0]), "r"(b[1]));
}

// -------------------- conv1 + gelu + maxpool(14) ---------------------------
__global__ void conv1_pool_kernel(const float* __restrict__ spec,
                                  const float* __restrict__ w1,
                                  const float* __restrict__ b1,
                                  float* __restrict__ p1) {
    int t  = blockIdx.x * 256 + threadIdx.x;
    int hp = blockIdx.y;
    int bc = blockIdx.z;
    int b = bc >> 5, c = bc & 31;
    __shared__ float w[25];
    if (threadIdx.x < 25) w[threadIdx.x] = w1[c * 25 + threadIdx.x];
    __syncthreads();
    if (t >= Tn) return;
    float bias = b1[c];
    float mx = -1e30f;
    #pragma unroll 1
    for (int hh = 0; hh < 14; hh++) {
        int h = hp * 14 + hh;
        float acc = bias;
        #pragma unroll
        for (int kh = 0; kh < 5; kh++) {
            int hi = h + kh - 2;
            if (hi < 0 || hi >= 196) continue;
            const float* srow = spec + ((size_t)b * 196 + hi) * Tn;
            #pragma unroll
            for (int kw = 0; kw < 5; kw++) {
                int ti = t + kw - 2;
                if (ti >= 0 && ti < Tn) acc += srow[ti] * w[kh * 5 + kw];
            }
        }
        mx = fmaxf(mx, gelu_exact(acc));
    }
    p1[(((size_t)(b * 32 + c)) * 14 + hp) * Tn + t] = mx;
}

// -------------------- conv2 + gelu (4 outputs per thread) ------------------
__global__ void conv2_kernel(const float* __restrict__ p1,
                             const float* __restrict__ w2,
                             const float* __restrict__ b2,
                             float* __restrict__ c2) {
    int t0 = threadIdx.x * 4;
    int h = blockIdx.y;
    int z = blockIdx.z;
    int b = z >> 6, co = z & 63;
    __shared__ float ws[800];
    for (int i = threadIdx.x; i < 800; i += 256) ws[i] = w2[(size_t)co * 800 + i];
    __syncthreads();
    if (t0 >= Tn) return;
    float bias = b2[co];
    float acc[4] = {bias, bias, bias, bias};
    #pragma unroll 1
    for (int ci = 0; ci < 32; ci++) {
        const float* pbase = p1 + ((size_t)(b * 32 + ci) * 14) * Tn;
        const float* wci = ws + ci * 25;
        #pragma unroll
        for (int kh = 0; kh < 5; kh++) {
            int hi = h + kh - 2;
            if (hi < 0 || hi >= 14) continue;
            const float* prow = pbase + (size_t)hi * Tn;
            const float* wrow = wci + kh * 5;
            float in[8];
            #pragma unroll
            for (int u = 0; u < 8; u++) {
                int ti = t0 - 2 + u;
                in[u] = (ti >= 0 && ti < Tn) ? prow[ti] : 0.f;
            }
            #pragma unroll
            for (int kw = 0; kw < 5; kw++) {
                float wv = wrow[kw];
                acc[0] += in[kw + 0] * wv;
                acc[1] += in[kw + 1] * wv;
                acc[2] += in[kw + 2] * wv;
                acc[3] += in[kw + 3] * wv;
            }
        }
    }
    float* orow = c2 + (((size_t)z) * 14 + h) * Tn;
    #pragma unroll
    for (int o = 0; o < 4; o++)
        if (t0 + o < Tn) orow[t0 + o] = gelu_exact(acc[o]);
}

// -------------------- pool over h (14 -> 1), write transposed --------------
__global__ void pool2t_kernel(const float* __restrict__ c2, float* __restrict__ pt) {
    int idx = blockIdx.x * 256 + threadIdx.x;
    if (idx >= Bn * 64 * Tn) return;
    int t = idx % Tn;
    int z = idx / Tn;
    int b = z >> 6, c = z & 63;
    const float* base = c2 + (size_t)z * 14 * Tn + t;
    float m = -1e30f;
    #pragma unroll
    for (int h = 0; h < 14; h++) m = fmaxf(m, base[(size_t)h * Tn]);
    pt[((size_t)b * Tn + t) * 64 + c] = m;
}

// -------------------- layernorm: warp per row (512 cols) -------------------
__global__ void ln_warp(const float* __restrict__ x,
                        const float* __restrict__ g,
                        const float* __restrict__ bta,
                        float* __restrict__ y) {
    int w = threadIdx.x >> 5, lane = threadIdx.x & 31;
    int row = blockIdx.x * 8 + w;
    const float* xr = x + (size_t)row * DMn;
    float4 v[4];
    float sum = 0.f;
    #pragma unroll
    for (int j = 0; j < 4; j++) {
        v[j] = *(const float4*)(xr + lane * 4 + j * 128);
        sum += v[j].x + v[j].y + v[j].z + v[j].w;
    }
    #pragma unroll
    for (int o = 16; o; o >>= 1) sum += __shfl_xor_sync(0xffffffffu, sum, o);
    float mu = sum * (1.0f / DMn);
    float vs = 0.f;
    #pragma unroll
    for (int j = 0; j < 4; j++) {
        v[j].x -= mu; v[j].y -= mu; v[j].z -= mu; v[j].w -= mu;
        vs += v[j].x * v[j].x + v[j].y * v[j].y + v[j].z * v[j].z + v[j].w * v[j].w;
    }
    #pragma unroll
    for (int o = 16; o; o >>= 1) vs += __shfl_xor_sync(0xffffffffu, vs, o);
    float inv = rsqrtf(vs * (1.0f / DMn) + 1e-5f);
    float* yr = y + (size_t)row * DMn;
    #pragma unroll
    for (int j = 0; j < 4; j++) {
        int c = lane * 4 + j * 128;
        float4 gg = *(const float4*)(g + c);
        float4 bb = *(const float4*)(bta + c);
        float4 o4;
        o4.x = gg.x * v[j].x * inv + bb.x;
        o4.y = gg.y * v[j].y * inv + bb.y;
        o4.z = gg.z * v[j].z * inv + bb.z;
        o4.w = gg.w * v[j].w * inv + bb.w;
        *(float4*)(yr + c) = o4;
    }
}

// -------------------- fp16x2 (Markidis) tensor-core GEMM -------------------
// C(MxN) = A(MxK) @ B(N,K)^T + bias; epi: 0 bias f32, 1 +relu f32,
// 2 +resid f32, 4 bias -> fp16 out
#define GBK 16
#define GPAD 20
__global__ __launch_bounds__(256, 2)
void hgemm2(const float* __restrict__ A, const float* __restrict__ B,
            const float* __restrict__ bias, const float* __restrict__ resid,
            void* __restrict__ Cv, int M, int N, int K,
            int lda, int ldb, int ldc, int epi)
{
    __shared__ __half Ahh[2][128][GPAD], All[2][128][GPAD];
    __shared__ __half Bhh[2][128][GPAD], Bll[2][128][GPAD];

    int tid = threadIdx.x, lane = tid & 31, w = tid >> 5;
    int warp_m = (w & 1) * 64, warp_n = (w >> 1) * 32;
    int brow = blockIdx.y * 128, bcol = blockIdx.x * 128;
    int g = lane >> 2, t2 = (lane & 3) * 2;

    float acc[4][4][4];
    #pragma unroll
    for (int a = 0; a < 4; a++)
        #pragma unroll
        for (int b2 = 0; b2 < 4; b2++)
            #pragma unroll
            for (int c2 = 0; c2 < 4; c2++) acc[a][b2][c2] = 0.f;

    int lr = tid >> 1, lh = (tid & 1) * 8;
    int ar = brow + lr, nbr = bcol + lr;
    const float4 f4z = make_float4(0.f, 0.f, 0.f, 0.f);

#define SPLIT8(dstH, dstL, buf, rowi, vals) { \
    _Pragma("unroll") \
    for (int e = 0; e < 4; e++) { \
        float x0 = vals[2*e], x1 = vals[2*e+1]; \
        __half h0 = __float2half_rn(x0), h1 = __float2half_rn(x1); \
        __half l0 = __float2half_rn(x0 - __half2float(h0)); \
        __half l1 = __float2half_rn(x1 - __half2float(h1)); \
        *(half2*)&dstH[buf][rowi][lh + 2*e] = __halves2half2(h0, h1); \
        *(half2*)&dstL[buf][rowi][lh + 2*e] = __halves2half2(l0, l1); \
    } }

#define LOADAB(buf, k0) { \
    float4 a0 = (ar < M) ? *(const float4*)(A + (size_t)ar * lda + (k0) + lh) : f4z; \
    float4 a1 = (ar < M) ? *(const float4*)(A + (size_t)ar * lda + (k0) + lh + 4) : f4z; \
    float4 b0 = (nbr < N) ? *(const float4*)(B + (size_t)nbr * ldb + (k0) + lh) : f4z; \
    float4 b1 = (nbr < N) ? *(const float4*)(B + (size_t)nbr * ldb + (k0) + lh + 4) : f4z; \
    float avv[8] = {a0.x,a0.y,a0.z,a0.w,a1.x,a1.y,a1.z,a1.w}; \
    float bvv[8] = {b0.x,b0.y,b0.z,b0.w,b1.x,b1.y,b1.z,b1.w}; \
    SPLIT8(Ahh, All, buf, lr, avv); \
    SPLIT8(Bhh, Bll, buf, lr, bvv); }

    LOADAB(0, 0);
    __syncthreads();

    int buf = 0;
    for (int k0 = GBK; k0 <= K; k0 += GBK) {
        bool more = (k0 < K);

        uint32_t bh[4][2], bl[4][2];
        #pragma unroll
        for (int nt = 0; nt < 4; nt++) {
            int col = warp_n + nt * 8 + g;
            bh[nt][0] = *(const uint32_t*)&Bhh[buf][col][t2];
            bh[nt][1] = *(const uint32_t*)&Bhh[buf][col][t2 + 8];
            bl[nt][0] = *(const uint32_t*)&Bll[buf][col][t2];
            bl[nt][1] = *(const uint32_t*)&Bll[buf][col][t2 + 8];
        }
        #pragma unroll
        for (int mt = 0; mt < 4; mt++) {
            int row = warp_m + mt * 16;
            uint32_t ah[4], al[4];
            ah[0] = *(const uint32_t*)&Ahh[buf][row + g][t2];
            ah[1] = *(const uint32_t*)&Ahh[buf][row + g + 8][t2];
            ah[2] = *(const uint32_t*)&Ahh[buf][row + g][t2 + 8];
            ah[3] = *(const uint32_t*)&Ahh[buf][row + g + 8][t2 + 8];
            al[0] = *(const uint32_t*)&All[buf][row + g][t2];
            al[1] = *(const uint32_t*)&All[buf][row + g + 8][t2];
            al[2] = *(const uint32_t*)&All[buf][row + g][t2 + 8];
            al[3] = *(const uint32_t*)&All[buf][row + g + 8][t2 + 8];
            #pragma unroll
            for (int nt = 0; nt < 4; nt++) {
                mma_f16(acc[mt][nt], ah, bl[nt]);
                mma_f16(acc[mt][nt], al, bh[nt]);
                mma_f16(acc[mt][nt], ah, bh[nt]);
            }
        }
        if (more) {
            buf ^= 1;
            LOADAB(buf, k0);
            __syncthreads();
        }
    }
#undef LOADAB
#undef SPLIT8

    #pragma unroll
    for (int mt = 0; mt < 4; mt++) {
        int r0 = brow + warp_m + mt * 16 + g;
        #pragma unroll
        for (int nt = 0; nt < 4; nt++) {
            int c0 = bcol + warp_n + nt * 8 + t2;
            #pragma unroll
            for (int half = 0; half < 2; half++) {
                int rr = r0 + half * 8;
                if (rr >= M) continue;
                #pragma unroll
                for (int jj = 0; jj < 2; jj++) {
                    int cc = c0 + jj;
                    if (cc >= N) continue;
                    float vv = acc[mt][nt][half * 2 + jj] + bias[cc];
                    if (epi == 1) vv = fmaxf(vv, 0.f);
                    else if (epi == 2) vv += resid[(size_t)rr * ldc + cc];
                    if (epi == 4) ((__half*)Cv)[(size_t)rr * ldc + cc] = __float2half_rn(vv);
                    else          ((float*)Cv)[(size_t)rr * ldc + cc] = vv;
                }
            }
        }
    }
}

// -------------------- Er fp32 -> fp16 --------------------------------------
__global__ void cvt_h_kernel(const float* __restrict__ src, __half* __restrict__ dst, int n) {
    int i = blockIdx.x * 256 + threadIdx.x;
    if (i < n) dst[i] = __float2half_rn(src[i]);
}

// -------------------- merged S/P score GEMM (fp16 in/out) ------------------
// z<32: C=S, B=K slice; z>=32: C=P, B=Erh. M=N=1000, K=64.
__global__ __launch_bounds__(256, 2)
void score_gemm_h(const __half* __restrict__ Q, const __half* __restrict__ Kh,
                  const __half* __restrict__ Erh,
                  __half* __restrict__ S, __half* __restrict__ P)
{
    int z = blockIdx.z;
    int bh = z & 31, b = bh >> 3, h = bh & 7;
    const __half* A = Q + (size_t)b * Tn * DMn + h * DEPTHn;
    const __half* Bp;
    int ldb;
    __half* C;
    if (z < 32) { Bp = Kh + (size_t)b * Tn * DMn + h * DEPTHn; ldb = DMn; C = S + (size_t)bh * Tn * Tn; }
    else        { Bp = Erh; ldb = DEPTHn; C = P + (size_t)bh * Tn * Tn; }
    const int lda = DMn, ldc = Tn;

    __shared__ __half As[128][72], Bs[128][72];
    int tid = threadIdx.x, lane = tid & 31, w = tid >> 5;
    int warp_m = (w & 1) * 64, warp_n = (w >> 1) * 32;
    int brow = blockIdx.y * 128, bcol = blockIdx.x * 128;
    int g = lane >> 2, t2 = (lane & 3) * 2;

    {
        int row = tid >> 1, cbase = (tid & 1) * 32;
        int arr = brow + row, brr = bcol + row;
        const uint4 u4z = make_uint4(0u, 0u, 0u, 0u);
        #pragma unroll
        for (int j = 0; j < 4; j++) {
            int col = cbase + j * 8;
            uint4 av = (arr < Tn) ? *(const uint4*)(A + (size_t)arr * lda + col) : u4z;
            uint4 bv = (brr < Tn) ? *(const uint4*)(Bp + (size_t)brr * ldb + col) : u4z;
            *(uint2*)&As[row][col]     = make_uint2(av.x, av.y);
            *(uint2*)&As[row][col + 4] = make_uint2(av.z, av.w);
            *(uint2*)&Bs[row][col]     = make_uint2(bv.x, bv.y);
            *(uint2*)&Bs[row][col + 4] = make_uint2(bv.z, bv.w);
        }
    }
    __syncthreads();

    float acc[4][4][4];
    #pragma unroll
    for (int a = 0; a < 4; a++)
        #pragma unroll
        for (int b2 = 0; b2 < 4; b2++)
            #pragma unroll
            for (int c2 = 0; c2 < 4; c2++) acc[a][b2][c2] = 0.f;

    #pragma unroll
    for (int ks = 0; ks < 4; ks++) {
        int k0 = ks * 16;
        uint32_t bf[4][2];
        #pragma unroll
        for (int nt = 0; nt < 4; nt++) {
            int col = warp_n + nt * 8 + g;
            bf[nt][0] = *(const uint32_t*)&Bs[col][k0 + t2];
            bf[nt][1] = *(const uint32_t*)&Bs[col][k0 + t2 + 8];
        }
        #pragma unroll
        for (int mt = 0; mt < 4; mt++) {
            int row = warp_m + mt * 16 + g;
            uint32_t af[4];
            af[0] = *(const uint32_t*)&As[row][k0 + t2];
            af[1] = *(const uint32_t*)&As[row + 8][k0 + t2];
            af[2] = *(const uint32_t*)&As[row][k0 + t2 + 8];
            af[3] = *(const uint32_t*)&As[row + 8][k0 + t2 + 8];
            #pragma unroll
            for (int nt = 0; nt < 4; nt++)
                mma_f16(acc[mt][nt], af, bf[nt]);
        }
    }

    #pragma unroll
    for (int mt = 0; mt < 4; mt++) {
        int r0 = brow + warp_m + mt * 16 + g;
        #pragma unroll
        for (int nt = 0; nt < 4; nt++) {
            int c0 = bcol + warp_n + nt * 8 + t2;
            if (c0 >= Tn) continue;
            #pragma unroll
            for (int half = 0; half < 2; half++) {
                int rr = r0 + half * 8;
                if (rr >= Tn) continue;
                *(half2*)&C[(size_t)rr * ldc + c0] =
                    __floats2half2_rn(acc[mt][nt][half * 2], acc[mt][nt][half * 2 + 1]);
            }
        }
    }
}

// -------------------- softmax with skew, warp-per-row, fp16 io -------------
__global__ void softmax_skew_h(const __half* __restrict__ S,
                               const __half* __restrict__ P,
                               __half* __restrict__ O) {
    int warp = threadIdx.x >> 5, lane = threadIdx.x & 31;
    int r = blockIdx.x * 8 + warp;
    int i = r % Tn;
    const __half* srow = S + (size_t)r * Tn;
    const __half* pi   = P + (size_t)r * Tn;
    const __half* pi1  = pi + Tn;

    float vals[32];
    float mx = -1e30f;
    #pragma unroll
    for (int j = 0; j < 32; j++) {
        int t = lane + j * 32;
        float lg = -1e30f;
        if (t < Tn) {
            float srel;
            if (t <= i)          srel = __half2float(pi[Tn - 1 - i + t]);
            else if (t == i + 1) srel = 0.f;
            else                 srel = __half2float(pi1[t - i - 2]);
            lg = (__half2float(srow[t]) + srel) * 0.125f;
        }
        vals[j] = lg;
        mx = fmaxf(mx, lg);
    }
    #pragma unroll
    for (int o = 16; o; o >>= 1) mx = fmaxf(mx, __shfl_xor_sync(0xffffffffu, mx, o));
    float sum = 0.f;
    #pragma unroll
    for (int j = 0; j < 32; j++) {
        float p = __expf(vals[j] - mx);
        vals[j] = p;
        sum += p;
    }
    #pragma unroll
    for (int o = 16; o; o >>= 1) sum += __shfl_xor_sync(0xffffffffu, sum, o);
    float inv = 1.0f / sum;
    __half* orow = O + (size_t)r * Tn;
    #pragma unroll
    for (int j = 0; j < 32; j++) {
        int t = lane + j * 32;
        if (t < Tn) orow[t] = __float2half_rn(vals[j] * inv);
    }
}

// -------------------- AV: O = probs(fp16) @ V(fp16) -> fp32 ----------------
#define AVPAD 40
__global__ __launch_bounds__(256, 2)
void av_gemm(const __half* __restrict__ Pr, const __half* __restrict__ V,
             float* __restrict__ O) {
    int bh = blockIdx.y;
    int b = bh >> 3, h = bh & 7;
    const __half* Ab = Pr + (size_t)bh * Tn * Tn;
    const __half* Vb = V + (size_t)b * Tn * DMn + h * DEPTHn;
    float* Ob = O + (size_t)b * Tn * DMn + h * DEPTHn;
    int i0 = blockIdx.x * 128;

    __shared__ __half As[2][128][AVPAD];
    __shared__ __half Bs[2][DEPTHn][AVPAD];

    int tid = threadIdx.x, lane = tid & 31, w = tid >> 5;
    int warp_m = (w & 3) * 32, warp_n = (w >> 2) * 32;
    int g = lane >> 2, t2 = (lane & 3) * 2;

    float acc[2][4][4];
    #pragma unroll
    for (int a = 0; a < 2; a++)
        #pragma unroll
        for (int b2 = 0; b2 < 4; b2++)
            #pragma unroll
            for (int c2 = 0; c2 < 4; c2++) acc[a][b2][c2] = 0.f;

    int arow = tid >> 1;
    int au   = (tid & 1) * 4;
    int bk   = tid >> 3;
    int bf4  = tid & 7;

#define AV_LOAD(buf, kt) { \
    int k0 = (kt) * 32; \
    int garow = i0 + arow; \
    _Pragma("unroll") \
    for (int j = 0; j < 4; j++) { \
        int kh = (au + j) * 4; \
        uint2 val = make_uint2(0u, 0u); \
        if (garow < Tn) { \
            if (k0 + kh + 3 < Tn) val = *(const uint2*)(Ab + (size_t)garow * Tn + k0 + kh); \
            else { \
                __half tmp[4]; \
                _Pragma("unroll") \
                for (int e = 0; e < 4; e++) \
                    tmp[e] = (k0 + kh + e < Tn) ? Ab[(size_t)garow * Tn + k0 + kh + e] : __half(0.f); \
                val = *(uint2*)tmp; \
            } \
        } \
        *(uint2*)&As[buf][arow][kh] = val; \
    } \
    { \
        int n0 = bf4 * 8; \
        int tg = k0 + bk; \
        uint4 vv = (tg < Tn) ? *(const uint4*)(Vb + (size_t)tg * DMn + n0) \
                             : make_uint4(0u, 0u, 0u, 0u); \
        __half hv[8]; *(uint4*)hv = vv; \
        _Pragma("unroll") \
        for (int e = 0; e < 8; e++) Bs[buf][n0 + e][bk] = hv[e]; \
    } }

    AV_LOAD(0, 0);
    __syncthreads();

    int buf = 0;
    for (int kt = 0; kt < 32; kt++) {
        bool more = (kt < 31);
        #pragma unroll
        for (int ks = 0; ks < 2; ks++) {
            int k0 = ks * 16;
            uint32_t bf[4][2];
            #pragma unroll
            for (int nt = 0; nt < 4; nt++) {
                int col = warp_n + nt * 8 + g;
                bf[nt][0] = *(const uint32_t*)&Bs[buf][col][k0 + t2];
                bf[nt][1] = *(const uint32_t*)&Bs[buf][col][k0 + t2 + 8];
            }
            #pragma unroll
            for (int mt = 0; mt < 2; mt++) {
                int row = warp_m + mt * 16 + g;
                uint32_t af[4];
                af[0] = *(const uint32_t*)&As[buf][row][k0 + t2];
                af[1] = *(const uint32_t*)&As[buf][row + 8][k0 + t2];
                af[2] = *(const uint32_t*)&As[buf][row][k0 + t2 + 8];
                af[3] = *(const uint32_t*)&As[buf][row + 8][k0 + t2 + 8];
                #pragma unroll
                for (int nt = 0; nt < 4; nt++)
                    mma_f16(acc[mt][nt], af, bf[nt]);
            }
        }
        if (more) {
            AV_LOAD(buf ^ 1, kt + 1);
            __syncthreads();
            buf ^= 1;
        }
    }
#undef AV_LOAD

    #pragma unroll
    for (int mt = 0; mt < 2; mt++) {
        int r0 = i0 + warp_m + mt * 16 + g;
        #pragma unroll
        for (int nt = 0; nt < 4; nt++) {
            int c0 = warp_n + nt * 8 + t2;
            #pragma unroll
            for (int half = 0; half < 2; half++) {
                int rr = r0 + half * 8;
                if (rr >= Tn) continue;
                Ob[(size_t)rr * DMn + c0]     = acc[mt][nt][half * 2];
                Ob[(size_t)rr * DMn + c0 + 1] = acc[mt][nt][half * 2 + 1];
            }
        }
    }
}

// ---------------------------------------------------------------------------
static void* symaddr(const void* sym) {
    void* p = nullptr;
    cudaGetSymbolAddress(&p, sym);
    return p;
}

extern "C" void kernel_launch(void* const* d_in, const int* in_sizes, int n_in,
                              void* d_out, int out_size) {
    const float* spec     = (const float*)d_in[0];
    const float* conv1_w  = (const float*)d_in[1];
    const float* conv1_b  = (const float*)d_in[2];
    const float* conv2_w  = (const float*)d_in[3];
    const float* conv2_b  = (const float*)d_in[4];
    const float* proj_w   = (const float*)d_in[5];
    const float* proj_b   = (const float*)d_in[6];
    const float* ln1_g    = (const float*)d_in[7];
    const float* ln1_b    = (const float*)d_in[8];
    const float* qw       = (const float*)d_in[9];
    const float* kw       = (const float*)d_in[10];
    const float* vw       = (const float*)d_in[11];
    const float* dw       = (const float*)d_in[12];
    const float* qb       = (const float*)d_in[13];
    const float* kb       = (const float*)d_in[14];
    const float* vb       = (const float*)d_in[15];
    const float* db       = (const float*)d_in[16];
    const float* Er       = (const float*)d_in[17];
    const float* ln2_g    = (const float*)d_in[18];
    const float* ln2_b    = (const float*)d_in[19];
    const float* f1w      = (const float*)d_in[20];
    const float* f1b      = (const float*)d_in[21];
    const float* f2w      = (const float*)d_in[22];
    const float* f2b      = (const float*)d_in[23];
    const float* deproj_w = (const float*)d_in[24];
    const float* deproj_b = (const float*)d_in[25];
    float* out = (float*)d_out;

    float*  p1  = (float*)symaddr(g_p1);
    float*  c2  = (float*)symaddr(g_c2);
    float*  pt  = (float*)symaddr(g_pt);
    float*  x   = (float*)symaddr(g_x);
    float*  xn  = (float*)symaddr(g_xn);
    __half* q   = (__half*)symaddr(g_q);
    __half* k   = (__half*)symaddr(g_k);
    __half* v   = (__half*)symaddr(g_v);
    float*  ao  = (float*)symaddr(g_ao);
    float*  ff  = (float*)symaddr(g_ff);
    __half* S   = (__half*)symaddr(g_S);
    __half* P   = (__half*)symaddr(g_P);
    __half* Erh = (__half*)symaddr(g_Erh);

    const int M = Bn * Tn;                // 4000

    conv1_pool_kernel<<<dim3(4, 14, Bn * 32), 256>>>(spec, conv1_w, conv1_b, p1);
    conv2_kernel<<<dim3(1, 14, Bn * 64), 256>>>(p1, conv2_w, conv2_b, c2);
    pool2t_kernel<<<dim3((Bn * 64 * Tn + 255) / 256), 256>>>(c2, pt);
    hgemm2<<<dim3(4, 32), 256>>>(pt, proj_w, proj_b, nullptr, x,
                                 M, DMn, 64, 64, 64, DMn, 0);

    dim3 g512(4, 32);
    dim3 gffn(16, 32);
    dim3 gscore(8, 8, 64);

    for (int l = 0; l < Ln; l++) {
        const float* qwl = qw + (size_t)l * DMn * DMn;
        const float* kwl = kw + (size_t)l * DMn * DMn;
        const float* vwl = vw + (size_t)l * DMn * DMn;
        const float* dwl = dw + (size_t)l * DMn * DMn;
        const float* Erl = Er + (size_t)l * Tn * DEPTHn;

        ln_warp<<<500, 256>>>(x, ln1_g + l * DMn, ln1_b + l * DMn, xn);
        hgemm2<<<g512, 256>>>(xn, qwl, qb + l * DMn, nullptr, q,
                              M, DMn, DMn, DMn, DMn, DMn, 4);
        hgemm2<<<g512, 256>>>(xn, kwl, kb + l * DMn, nullptr, k,
                              M, DMn, DMn, DMn, DMn, DMn, 4);
        hgemm2<<<g512, 256>>>(xn, vwl, vb + l * DMn, nullptr, v,
                              M, DMn, DMn, DMn, DMn, DMn, 4);
        cvt_h_kernel<<<250, 256>>>(Erl, Erh, Tn * DEPTHn);

        score_gemm_h<<<gscore, 256>>>(q, k, Erh, S, P);
        softmax_skew_h<<<Bn * Hn * Tn / 8, 256>>>(S, P, S);
        av_gemm<<<dim3(8, Bn * Hn), 256>>>(S, v, ao);

        hgemm2<<<g512, 256>>>(ao, dwl, db + l * DMn, x, x,
                              M, DMn, DMn, DMn, DMn, DMn, 2);
        ln_warp<<<500, 256>>>(x, ln2_g + l * DMn, ln2_b + l * DMn, xn);
        hgemm2<<<gffn, 256>>>(xn, f1w + (size_t)l * FFNn * DMn, f1b + l * FFNn,
                              nullptr, ff, M, FFNn, DMn, DMn, DMn, FFNn, 1);
        hgemm2<<<g512, 256>>>(ff, f2w + (size_t)l * DMn * FFNn, f2b + l * DMn,
                              x, x, M, DMn, FFNn, FFNn, FFNn, DMn, 2);
    }

    hgemm2<<<dim3(1, 32), 256>>>(x, deproj_w, deproj_b, nullptr, out,
                                 M, EDIMn, DMn, DMn, DMn, EDIMn, 0);
}